// round 12
// baseline (speedup 1.0000x reference)
#include <cuda_runtime.h>
#include <math.h>
#include <stdint.h>

#define Bc 2
#define Sc 2048
#define Dc 1024
#define Hc 16
#define DHc 64
#define Ec 8
#define FHc 4096
#define Tc (Bc*Sc)   // 4096 tokens

// ---------------- scratch (device globals; no allocations) ----------------
__device__ float g_ln1[Tc*Dc];
__device__ float g_q[Tc*Dc];
__device__ float g_k[Tc*Dc];
__device__ float g_v[Tc*Dc];
__device__ float g_attn[Tc*Dc];
__device__ float g_res1[Tc*Dc];
__device__ float g_ln2[Tc*Dc];       // fp32 (for routing)
__device__ float g_ln2r[Tc*Dc];      // tf32-rounded (GEMM A operand)
__device__ float g_h[(size_t)Tc*FHc];
__device__ float g_y[(size_t)Ec*Tc*Dc];
__device__ int   g_cnt[Ec];
__device__ float g_pmean[Ec];
__device__ int   g_list[Ec*Tc];
__device__ int   g_te[2*Tc];
__device__ int   g_pos[2*Tc];
__device__ float g_tw[2*Tc];

__global__ void init_k() {
    int i = threadIdx.x;
    if (i < Ec) { g_cnt[i] = 0; g_pmean[i] = 0.f; }
}

// ---------------- helpers ----------------
__device__ __forceinline__ uint32_t f2tf32(float x) {
    uint32_t r;
    asm("cvt.rna.tf32.f32 %0, %1;" : "=r"(r) : "f"(x));
    return r;
}
__device__ __forceinline__ float f2tf32f(float x) {
    return __uint_as_float(f2tf32(x));
}
__device__ __forceinline__ void mma_tf32(float* c, const uint32_t* a, const uint32_t* b) {
    asm volatile(
        "mma.sync.aligned.m16n8k8.row.col.f32.tf32.tf32.f32 "
        "{%0,%1,%2,%3}, {%4,%5,%6,%7}, {%8,%9}, {%0,%1,%2,%3};"
        : "+f"(c[0]), "+f"(c[1]), "+f"(c[2]), "+f"(c[3])
        : "r"(a[0]), "r"(a[1]), "r"(a[2]), "r"(a[3]), "r"(b[0]), "r"(b[1]));
}
__device__ __forceinline__ float gelu_f(float x) {
    float x3 = x * x * x;
    float t = tanhf(0.7978845608028654f * (x + 0.044715f * x3));
    return 0.5f * x * (1.0f + t);
}

// ---------------- LayerNorm ----------------
// DUAL=false: write tf32-rounded to out. DUAL=true: fp32 to out, rounded to out2.
template<bool DUAL>
__global__ void ln_k(const float* __restrict__ in, const float* __restrict__ sc,
                     const float* __restrict__ bi, float* __restrict__ out,
                     float* __restrict__ out2) {
    __shared__ float xs[Dc];
    __shared__ float red[256];
    int t = blockIdx.x, tid = threadIdx.x;
    const float* r = in + (size_t)t * Dc;
    float s = 0.f;
    for (int d = tid; d < Dc; d += 256) { float v = r[d]; xs[d] = v; s += v; }
    red[tid] = s; __syncthreads();
    for (int o = 128; o > 0; o >>= 1) { if (tid < o) red[tid] += red[tid + o]; __syncthreads(); }
    float mu = red[0] * (1.0f / Dc);
    __syncthreads();
    float s2 = 0.f;
    for (int d = tid; d < Dc; d += 256) { float dv = xs[d] - mu; s2 += dv * dv; }
    red[tid] = s2; __syncthreads();
    for (int o = 128; o > 0; o >>= 1) { if (tid < o) red[tid] += red[tid + o]; __syncthreads(); }
    float inv = rsqrtf(red[0] * (1.0f / Dc) + 1e-6f);
    float* orow = out + (size_t)t * Dc;
    float* orow2 = DUAL ? (out2 + (size_t)t * Dc) : nullptr;
    for (int d = tid; d < Dc; d += 256) {
        float v = (xs[d] - mu) * inv * sc[d] + bi[d];
        if (DUAL) { orow[d] = v; orow2[d] = f2tf32f(v); }
        else      { orow[d] = f2tf32f(v); }
    }
}

// ---------------- TF32 mma.sync GEMM: 128x128 tile, 8 warps x 32x64 ----------------
// Register-staged double buffer (R7/R10-proven path), launch_bounds(256) so ptxas
// gets full register budget (R8's spill was the (256,2)=128-reg cap).
// A must be pre-rounded tf32; B (weights) rounded on the fly in sstore.
// EPI: 0 bias; 1 bias+res; 2 bias+gelu. ROUND: round C store to tf32.
#define TBM 128
#define TBN 128
#define TBK 32
#define ASTR 36
#define BSTR 132
#define ABUF (TBM*ASTR)            // 4608 floats
#define BBUF (TBK*BSTR)            // 4224 floats
#define TGEMM_SMEM ((2*ABUF + 2*BBUF) * 4)   // 70656 bytes

template<int EPI, bool GATHER, int ROUND>
__global__ __launch_bounds__(256) void tmma_k(
    const float* __restrict__ A, const float* __restrict__ B,
    const float* __restrict__ bias, const float* __restrict__ res,
    float* __restrict__ C, int M, int N, int Kd,
    const int* __restrict__ ridx, const int* __restrict__ mcnt)
{
    int Meff = mcnt ? *mcnt : M;
    int row0 = blockIdx.y * TBM;
    if (row0 >= Meff) return;
    int col0 = blockIdx.x * TBN;

    extern __shared__ float smem[];
    float* As = smem;              // [2][ABUF]
    float* Bs = smem + 2 * ABUF;   // [2][BBUF]

    int tid  = threadIdx.x;
    int wid  = tid >> 5;
    int lane = tid & 31;

    // ---- loader setup: 256 threads ----
    // A: row = tid>>1 (0..127), half (tid&1)*16 floats -> 4 float4 each
    int ra = tid >> 1;
    int ha = (tid & 1) * 16;
    int gra = row0 + ra;
    int cra = gra < Meff ? gra : Meff - 1;
    int srca = GATHER ? ridx[cra] : cra;
    const float* arowp = A + (size_t)srca * Kd + ha;
    // B: k-row = tid>>3 (0..31), col chunk (tid&7)*16 floats -> 4 float4 each
    int rb = tid >> 3;
    int cb = (tid & 7) * 16;
    const float* bptr = B + (size_t)rb * N + col0 + cb;

    float4 aR[4]; float4 bR[4];
    auto gload = [&](int c) {
        const float* as = arowp + c * TBK;
#pragma unroll
        for (int i = 0; i < 4; i++) aR[i] = *(const float4*)(as + i * 4);
        const float* bs = bptr + (size_t)c * TBK * N;
#pragma unroll
        for (int i = 0; i < 4; i++) bR[i] = *(const float4*)(bs + i * 4);
    };
    auto sstore = [&](int b) {
        float* Ab = As + b * ABUF;
        float* Bb = Bs + b * BBUF;
#pragma unroll
        for (int i = 0; i < 4; i++)
            *(float4*)(Ab + ra * ASTR + ha + i * 4) = aR[i];           // A pre-rounded
#pragma unroll
        for (int i = 0; i < 4; i++) {
            uint4 v = make_uint4(f2tf32(bR[i].x), f2tf32(bR[i].y),
                                 f2tf32(bR[i].z), f2tf32(bR[i].w));    // round weights here
            *(uint4*)(Bb + rb * BSTR + cb + i * 4) = v;
        }
    };

    // ---- compute setup: warp tile 32x64 (4 warps M, 2 warps N) ----
    int g = lane >> 2, t = lane & 3;
    int m0 = (wid & 3) * 32;
    int n0 = (wid >> 2) * 64;
    float acc[2][8][4];
#pragma unroll
    for (int mt = 0; mt < 2; mt++)
#pragma unroll
        for (int nt = 0; nt < 8; nt++)
#pragma unroll
            for (int i = 0; i < 4; i++) acc[mt][nt][i] = 0.f;

    auto compute = [&](int b) {
        const uint32_t* Ab = (const uint32_t*)(As + b * ABUF);
        const uint32_t* Bb = (const uint32_t*)(Bs + b * BBUF);
#pragma unroll
        for (int kk = 0; kk < TBK; kk += 8) {
            uint32_t af[2][4], bf[8][2];
#pragma unroll
            for (int mt = 0; mt < 2; mt++) {
                int base = (m0 + mt * 16 + g) * ASTR + kk + t;
                af[mt][0] = Ab[base];
                af[mt][1] = Ab[base + 8 * ASTR];
                af[mt][2] = Ab[base + 4];
                af[mt][3] = Ab[base + 8 * ASTR + 4];
            }
#pragma unroll
            for (int nt = 0; nt < 8; nt++) {
                int nb = n0 + nt * 8 + g;
                bf[nt][0] = Bb[(kk + t) * BSTR + nb];
                bf[nt][1] = Bb[(kk + t + 4) * BSTR + nb];
            }
#pragma unroll
            for (int mt = 0; mt < 2; mt++)
#pragma unroll
                for (int nt = 0; nt < 8; nt++)
                    mma_tf32(acc[mt][nt], af[mt], bf[nt]);
        }
    };

    // ---- pipelined main loop: ONE sync per chunk (R7-proven hazard analysis) ----
    const int NC = Kd / TBK;
    gload(0); sstore(0);
    __syncthreads();
    for (int c = 0; c < NC; c++) {
        if (c + 1 < NC) gload(c + 1);
        compute(c & 1);
        if (c + 1 < NC) sstore((c + 1) & 1);
        __syncthreads();
    }

    // ---- epilogue ----
#pragma unroll
    for (int mt = 0; mt < 2; mt++) {
#pragma unroll
        for (int hrow = 0; hrow < 2; hrow++) {
            int gr = row0 + m0 + mt * 16 + hrow * 8 + g;
            if (gr >= Meff) continue;
            float* crow = C + (size_t)gr * N;
            const float* rrow = (EPI == 1) ? (res + (size_t)gr * N) : nullptr;
#pragma unroll
            for (int nt = 0; nt < 8; nt++) {
                int gc = col0 + n0 + nt * 8 + 2 * t;
                float v0 = acc[mt][nt][hrow * 2 + 0] + bias[gc];
                float v1 = acc[mt][nt][hrow * 2 + 1] + bias[gc + 1];
                if (EPI == 1) { v0 += rrow[gc]; v1 += rrow[gc + 1]; }
                if (EPI == 2) { v0 = gelu_f(v0); v1 = gelu_f(v1); }
                if (ROUND)    { v0 = f2tf32f(v0); v1 = f2tf32f(v1); }
                *(float2*)(crow + gc) = make_float2(v0, v1);
            }
        }
    }
}

// ---------------- TF32 tensor-core causal flash attention ----------------
#define KSTR 68
#define ATT_SMEM ((3*64*KSTR + 4*16*KSTR) * 4)

__global__ __launch_bounds__(128) void attn_tc_k(
    const float* __restrict__ q, const float* __restrict__ k,
    const float* __restrict__ v, float* __restrict__ o)
{
    extern __shared__ float sm[];
    float* Qs = sm;
    float* Ks = sm + 64 * KSTR;
    float* Vs = sm + 2 * 64 * KSTR;
    float* Ps = sm + 3 * 64 * KSTR;

    int bh = blockIdx.y;
    int b = bh >> 4, h = bh & 15;
    int qb = blockIdx.x * 64;
    int tid = threadIdx.x, wid = tid >> 5, lane = tid & 31;
    int g = lane >> 2, t = lane & 3;
    size_t base = ((size_t)b * Sc) * Dc + h * DHc;

#pragma unroll
    for (int i = 0; i < 8; i++) {
        int idx = tid + i * 128;
        int r = idx >> 4, c4 = (idx & 15) * 4;
        float4 val = *(const float4*)(q + base + (size_t)(qb + r) * Dc + c4);
        uint32_t* dst = (uint32_t*)(Qs + r * KSTR + c4);
        dst[0] = f2tf32(val.x * 0.125f); dst[1] = f2tf32(val.y * 0.125f);
        dst[2] = f2tf32(val.z * 0.125f); dst[3] = f2tf32(val.w * 0.125f);
    }
    __syncthreads();

    int qrow = wid * 16;
    uint32_t qf[8][4];
    {
        const uint32_t* Q32 = (const uint32_t*)Qs;
#pragma unroll
        for (int kc = 0; kc < 8; kc++) {
            int base0 = (qrow + g) * KSTR + kc * 8 + t;
            qf[kc][0] = Q32[base0];
            qf[kc][1] = Q32[base0 + 8 * KSTR];
            qf[kc][2] = Q32[base0 + 4];
            qf[kc][3] = Q32[base0 + 8 * KSTR + 4];
        }
    }

    float oa[8][4];
#pragma unroll
    for (int nt = 0; nt < 8; nt++)
#pragma unroll
        for (int i = 0; i < 4; i++) oa[nt][i] = 0.f;
    float m0 = -1e30f, m1 = -1e30f, l0 = 0.f, l1 = 0.f;
    int r0 = qb + qrow + g, r1 = r0 + 8;

    int ntiles = qb / 64 + 1;
    float* Pw = Ps + wid * 16 * KSTR;
    uint32_t* Pw32 = (uint32_t*)Pw;
    const uint32_t* K32 = (const uint32_t*)Ks;
    const uint32_t* V32 = (const uint32_t*)Vs;

    for (int tile = 0; tile < ntiles; tile++) {
        int j0 = tile * 64;
        __syncthreads();
#pragma unroll
        for (int i = 0; i < 8; i++) {
            int idx = tid + i * 128;
            int r = idx >> 4, c4 = (idx & 15) * 4;
            size_t goff = base + (size_t)(j0 + r) * Dc + c4;
            float4 kv = *(const float4*)(k + goff);
            float4 vv = *(const float4*)(v + goff);
            uint32_t* kd = (uint32_t*)(Ks + r * KSTR + c4);
            uint32_t* vd = (uint32_t*)(Vs + r * KSTR + c4);
            kd[0] = f2tf32(kv.x); kd[1] = f2tf32(kv.y); kd[2] = f2tf32(kv.z); kd[3] = f2tf32(kv.w);
            vd[0] = f2tf32(vv.x); vd[1] = f2tf32(vv.y); vd[2] = f2tf32(vv.z); vd[3] = f2tf32(vv.w);
        }
        __syncthreads();

        float s[8][4];
#pragma unroll
        for (int nt = 0; nt < 8; nt++) {
            s[nt][0] = s[nt][1] = s[nt][2] = s[nt][3] = 0.f;
            const uint32_t* krow = K32 + (nt * 8 + g) * KSTR;
#pragma unroll
            for (int kc = 0; kc < 8; kc++) {
                uint32_t bf[2] = { krow[kc * 8 + t], krow[kc * 8 + t + 4] };
                mma_tf32(s[nt], qf[kc], bf);
            }
        }
        if (j0 == qb) {
#pragma unroll
            for (int nt = 0; nt < 8; nt++) {
                int cbp = j0 + nt * 8 + 2 * t;
                if (cbp > r0)     s[nt][0] = -1e30f;
                if (cbp + 1 > r0) s[nt][1] = -1e30f;
                if (cbp > r1)     s[nt][2] = -1e30f;
                if (cbp + 1 > r1) s[nt][3] = -1e30f;
            }
        }
        float mt0 = -1e30f, mt1 = -1e30f;
#pragma unroll
        for (int nt = 0; nt < 8; nt++) {
            mt0 = fmaxf(mt0, fmaxf(s[nt][0], s[nt][1]));
            mt1 = fmaxf(mt1, fmaxf(s[nt][2], s[nt][3]));
        }
#pragma unroll
        for (int off = 1; off <= 2; off <<= 1) {
            mt0 = fmaxf(mt0, __shfl_xor_sync(0xffffffffu, mt0, off));
            mt1 = fmaxf(mt1, __shfl_xor_sync(0xffffffffu, mt1, off));
        }
        float mn0 = fmaxf(m0, mt0), mn1 = fmaxf(m1, mt1);
        float c0 = __expf(m0 - mn0), c1 = __expf(m1 - mn1);
        m0 = mn0; m1 = mn1;
        l0 *= c0; l1 *= c1;
#pragma unroll
        for (int nt = 0; nt < 8; nt++) {
            oa[nt][0] *= c0; oa[nt][1] *= c0;
            oa[nt][2] *= c1; oa[nt][3] *= c1;
        }
#pragma unroll
        for (int nt = 0; nt < 8; nt++) {
            float p0 = __expf(s[nt][0] - m0);
            float p1 = __expf(s[nt][1] - m0);
            float p2 = __expf(s[nt][2] - m1);
            float p3 = __expf(s[nt][3] - m1);
            l0 += p0 + p1; l1 += p2 + p3;
            int cbp = nt * 8 + 2 * t;
            *(uint2*)(Pw32 + g * KSTR + cbp)       = make_uint2(f2tf32(p0), f2tf32(p1));
            *(uint2*)(Pw32 + (g + 8) * KSTR + cbp) = make_uint2(f2tf32(p2), f2tf32(p3));
        }
        __syncwarp();
        uint32_t af[8][4];
#pragma unroll
        for (int kc = 0; kc < 8; kc++) {
            int base0 = g * KSTR + kc * 8 + t;
            af[kc][0] = Pw32[base0];
            af[kc][1] = Pw32[base0 + 8 * KSTR];
            af[kc][2] = Pw32[base0 + 4];
            af[kc][3] = Pw32[base0 + 8 * KSTR + 4];
        }
#pragma unroll
        for (int nt = 0; nt < 8; nt++) {
#pragma unroll
            for (int kc = 0; kc < 8; kc++) {
                uint32_t bf[2] = { V32[(kc * 8 + t) * KSTR + nt * 8 + g],
                                   V32[(kc * 8 + t + 4) * KSTR + nt * 8 + g] };
                mma_tf32(oa[nt], af[kc], bf);
            }
        }
        __syncwarp();
    }

#pragma unroll
    for (int off = 1; off <= 2; off <<= 1) {
        l0 += __shfl_xor_sync(0xffffffffu, l0, off);
        l1 += __shfl_xor_sync(0xffffffffu, l1, off);
    }
    float i0 = 1.f / l0, i1 = 1.f / l1;
    float* o0 = o + base + (size_t)r0 * Dc;
    float* o1 = o + base + (size_t)r1 * Dc;
#pragma unroll
    for (int nt = 0; nt < 8; nt++) {
        int cbp = nt * 8 + 2 * t;
        *(float2*)(o0 + cbp) = make_float2(f2tf32f(oa[nt][0] * i0), f2tf32f(oa[nt][1] * i0));
        *(float2*)(o1 + cbp) = make_float2(f2tf32f(oa[nt][2] * i1), f2tf32f(oa[nt][3] * i1));
    }
}

// ---------------- MoE routing (consumes fp32 ln2) ----------------
__global__ void route_k(const float* __restrict__ ln2,
                        const float* __restrict__ Wg, const float* __restrict__ bg) {
    int t = blockIdx.x;
    int tid = threadIdx.x;
    int w = tid >> 5, lane = tid & 31;
    const float* xr = ln2 + (size_t)t * Dc;
    float s = 0.f;
    for (int d = lane; d < Dc; d += 32) s += xr[d] * Wg[d * Ec + w];
#pragma unroll
    for (int off = 16; off > 0; off >>= 1) s += __shfl_down_sync(0xffffffffu, s, off);
    __shared__ float lg[Ec];
    if (lane == 0) lg[w] = s + bg[w];
    __syncthreads();
    if (tid == 0) {
        float mx = lg[0];
        for (int e = 1; e < Ec; e++) mx = fmaxf(mx, lg[e]);
        float p[Ec]; float sum = 0.f;
        for (int e = 0; e < Ec; e++) { p[e] = __expf(lg[e] - mx); sum += p[e]; }
        float inv = 1.f / sum;
        for (int e = 0; e < Ec; e++) { p[e] *= inv; atomicAdd(&g_pmean[e], p[e]); }
        int e0 = 0; for (int e = 1; e < Ec; e++) if (p[e] > p[e0]) e0 = e;
        int e1 = (e0 == 0) ? 1 : 0;
        for (int e = 0; e < Ec; e++) if (e != e0 && p[e] > p[e1]) e1 = e;
        float w0 = p[e0], w1 = p[e1], wn = 1.f / (w0 + w1);
        w0 *= wn; w1 *= wn;
        int s0 = atomicAdd(&g_cnt[e0], 1);
        int s1 = atomicAdd(&g_cnt[e1], 1);
        g_list[e0 * Tc + s0] = t; g_list[e1 * Tc + s1] = t;
        g_te[2*t] = e0; g_te[2*t+1] = e1;
        g_pos[2*t] = s0; g_pos[2*t+1] = s1;
        g_tw[2*t] = w0; g_tw[2*t+1] = w1;
    }
}

// ---------------- combine & aux ----------------
__global__ void combine_k(float* __restrict__ out) {
    int t = blockIdx.x;
    int e0 = g_te[2*t], e1 = g_te[2*t+1];
    int s0 = g_pos[2*t], s1 = g_pos[2*t+1];
    float w0 = g_tw[2*t], w1 = g_tw[2*t+1];
    const float* y0 = g_y + ((size_t)e0 * Tc + s0) * Dc;
    const float* y1 = g_y + ((size_t)e1 * Tc + s1) * Dc;
    const float* r  = g_res1 + (size_t)t * Dc;
    float* o = out + (size_t)t * Dc;
    for (int d = threadIdx.x; d < Dc; d += 256)
        o[d] = r[d] + w0 * y0[d] + w1 * y1[d];
}

__global__ void aux_k(float* __restrict__ out) {
    if (threadIdx.x == 0) {
        float a = 0.f;
        for (int e = 0; e < Ec; e++) a += (float)g_cnt[e] * g_pmean[e];
        out[0] = 0.01f * (float)Ec * a / ((float)Tc * (float)Tc);
    }
}

// ---------------- launch ----------------
extern "C" void kernel_launch(void* const* d_in, const int* in_sizes, int n_in,
                              void* d_out, int out_size) {
    (void)in_sizes; (void)n_in;
    const float* x   = (const float*)d_in[0];
    const float* l1s = (const float*)d_in[1];
    const float* l1b = (const float*)d_in[2];
    const float* Wq  = (const float*)d_in[3];
    const float* bq  = (const float*)d_in[4];
    const float* Wk  = (const float*)d_in[5];
    const float* bk  = (const float*)d_in[6];
    const float* Wv  = (const float*)d_in[7];
    const float* bv  = (const float*)d_in[8];
    const float* Wo  = (const float*)d_in[9];
    const float* bo  = (const float*)d_in[10];
    const float* l2s = (const float*)d_in[11];
    const float* l2b = (const float*)d_in[12];
    const float* Wg  = (const float*)d_in[13];
    const float* bg  = (const float*)d_in[14];
    const float* W1  = (const float*)d_in[15];
    const float* b1  = (const float*)d_in[16];
    const float* W2  = (const float*)d_in[17];
    const float* b2  = (const float*)d_in[18];
    float* out = (float*)d_out;

    float *ln1, *qb_, *kb_, *vb_, *attn, *res1, *ln2, *ln2r, *hb, *yb;
    int *lst, *cnt;
    cudaGetSymbolAddress((void**)&ln1,  g_ln1);
    cudaGetSymbolAddress((void**)&qb_,  g_q);
    cudaGetSymbolAddress((void**)&kb_,  g_k);
    cudaGetSymbolAddress((void**)&vb_,  g_v);
    cudaGetSymbolAddress((void**)&attn, g_attn);
    cudaGetSymbolAddress((void**)&res1, g_res1);
    cudaGetSymbolAddress((void**)&ln2,  g_ln2);
    cudaGetSymbolAddress((void**)&ln2r, g_ln2r);
    cudaGetSymbolAddress((void**)&hb,   g_h);
    cudaGetSymbolAddress((void**)&yb,   g_y);
    cudaGetSymbolAddress((void**)&lst,  g_list);
    cudaGetSymbolAddress((void**)&cnt,  g_cnt);

    cudaFuncSetAttribute((const void*)tmma_k<0,false,1>, cudaFuncAttributeMaxDynamicSharedMemorySize, TGEMM_SMEM);
    cudaFuncSetAttribute((const void*)tmma_k<1,false,0>, cudaFuncAttributeMaxDynamicSharedMemorySize, TGEMM_SMEM);
    cudaFuncSetAttribute((const void*)tmma_k<0,false,0>, cudaFuncAttributeMaxDynamicSharedMemorySize, TGEMM_SMEM);
    cudaFuncSetAttribute((const void*)tmma_k<2,true,1>,  cudaFuncAttributeMaxDynamicSharedMemorySize, TGEMM_SMEM);
    cudaFuncSetAttribute((const void*)attn_tc_k,         cudaFuncAttributeMaxDynamicSharedMemorySize, ATT_SMEM);

    init_k<<<1, 32>>>();
    ln_k<false><<<Tc, 256>>>(x, l1s, l1b, ln1, nullptr);

    dim3 gD(Dc / TBN, Tc / TBM);   // (8, 32)
    tmma_k<0,false,1><<<gD, 256, TGEMM_SMEM>>>(ln1, Wq, bq, nullptr, qb_, Tc, Dc, Dc, nullptr, nullptr);
    tmma_k<0,false,1><<<gD, 256, TGEMM_SMEM>>>(ln1, Wk, bk, nullptr, kb_, Tc, Dc, Dc, nullptr, nullptr);
    tmma_k<0,false,1><<<gD, 256, TGEMM_SMEM>>>(ln1, Wv, bv, nullptr, vb_, Tc, Dc, Dc, nullptr, nullptr);

    attn_tc_k<<<dim3(Sc / 64, Bc * Hc), 128, ATT_SMEM>>>(qb_, kb_, vb_, attn);

    tmma_k<1,false,0><<<gD, 256, TGEMM_SMEM>>>(attn, Wo, bo, x, res1, Tc, Dc, Dc, nullptr, nullptr);
    ln_k<true><<<Tc, 256>>>(res1, l2s, l2b, ln2, ln2r);   // fp32 for routing, rounded for GEMM
    route_k<<<Tc, 256>>>(ln2, Wg, bg);

    dim3 gF(FHc / TBN, Tc / TBM);  // (32, 32)
    for (int e = 0; e < Ec; e++) {
        tmma_k<2,true,1><<<gF, 256, TGEMM_SMEM>>>(ln2r, W1 + (size_t)e * Dc * FHc,
                                                  b1 + (size_t)e * FHc, nullptr, hb,
                                                  Tc, FHc, Dc, lst + e * Tc, cnt + e);
        tmma_k<0,false,0><<<gD, 256, TGEMM_SMEM>>>(hb, W2 + (size_t)e * FHc * Dc,
                                                   b2 + (size_t)e * Dc, nullptr,
                                                   yb + (size_t)e * Tc * Dc,
                                                   Tc, Dc, FHc, nullptr, cnt + e);
    }

    combine_k<<<Tc, 256>>>(out);
    if (out_size > Tc * Dc) aux_k<<<1, 32>>>(out + (size_t)Tc * Dc);
}

// round 13
// speedup vs baseline: 1.3169x; 1.3169x over previous
#include <cuda_runtime.h>
#include <math.h>
#include <stdint.h>

#define Bc 2
#define Sc 2048
#define Dc 1024
#define Hc 16
#define DHc 64
#define Ec 8
#define FHc 4096
#define Tc (Bc*Sc)   // 4096 tokens

// ---------------- scratch (device globals; no allocations) ----------------
__device__ float g_ln1[Tc*Dc];
__device__ float g_q[Tc*Dc];
__device__ float g_k[Tc*Dc];
__device__ float g_v[Tc*Dc];
__device__ float g_attn[Tc*Dc];
__device__ float g_res1[Tc*Dc];
__device__ float g_ln2[Tc*Dc];       // fp32 (for routing)
__device__ float g_ln2r[Tc*Dc];      // tf32-rounded (GEMM A operand)
__device__ float g_h[(size_t)Tc*FHc];
__device__ float g_y[(size_t)Ec*Tc*Dc];
__device__ int   g_cnt[Ec];
__device__ float g_pmean[Ec];
__device__ int   g_list[Ec*Tc];
__device__ int   g_te[2*Tc];
__device__ int   g_pos[2*Tc];
__device__ float g_tw[2*Tc];

__global__ void init_k() {
    int i = threadIdx.x;
    if (i < Ec) { g_cnt[i] = 0; g_pmean[i] = 0.f; }
}

// ---------------- helpers ----------------
__device__ __forceinline__ uint32_t f2tf32(float x) {
    uint32_t r;
    asm("cvt.rna.tf32.f32 %0, %1;" : "=r"(r) : "f"(x));
    return r;
}
__device__ __forceinline__ float f2tf32f(float x) {
    return __uint_as_float(f2tf32(x));
}
__device__ __forceinline__ void mma_tf32(float* c, const uint32_t* a, const uint32_t* b) {
    asm volatile(
        "mma.sync.aligned.m16n8k8.row.col.f32.tf32.tf32.f32 "
        "{%0,%1,%2,%3}, {%4,%5,%6,%7}, {%8,%9}, {%0,%1,%2,%3};"
        : "+f"(c[0]), "+f"(c[1]), "+f"(c[2]), "+f"(c[3])
        : "r"(a[0]), "r"(a[1]), "r"(a[2]), "r"(a[3]), "r"(b[0]), "r"(b[1]));
}
__device__ __forceinline__ float gelu_f(float x) {
    float x3 = x * x * x;
    float t = tanhf(0.7978845608028654f * (x + 0.044715f * x3));
    return 0.5f * x * (1.0f + t);
}

// ---------------- LayerNorm ----------------
// DUAL=false: write tf32-rounded to out. DUAL=true: fp32 to out, rounded to out2.
template<bool DUAL>
__global__ void ln_k(const float* __restrict__ in, const float* __restrict__ sc,
                     const float* __restrict__ bi, float* __restrict__ out,
                     float* __restrict__ out2) {
    __shared__ float xs[Dc];
    __shared__ float red[256];
    int t = blockIdx.x, tid = threadIdx.x;
    const float* r = in + (size_t)t * Dc;
    float s = 0.f;
    for (int d = tid; d < Dc; d += 256) { float v = r[d]; xs[d] = v; s += v; }
    red[tid] = s; __syncthreads();
    for (int o = 128; o > 0; o >>= 1) { if (tid < o) red[tid] += red[tid + o]; __syncthreads(); }
    float mu = red[0] * (1.0f / Dc);
    __syncthreads();
    float s2 = 0.f;
    for (int d = tid; d < Dc; d += 256) { float dv = xs[d] - mu; s2 += dv * dv; }
    red[tid] = s2; __syncthreads();
    for (int o = 128; o > 0; o >>= 1) { if (tid < o) red[tid] += red[tid + o]; __syncthreads(); }
    float inv = rsqrtf(red[0] * (1.0f / Dc) + 1e-6f);
    float* orow = out + (size_t)t * Dc;
    float* orow2 = DUAL ? (out2 + (size_t)t * Dc) : nullptr;
    for (int d = tid; d < Dc; d += 256) {
        float v = (xs[d] - mu) * inv * sc[d] + bi[d];
        if (DUAL) { orow[d] = v; orow2[d] = f2tf32f(v); }
        else      { orow[d] = f2tf32f(v); }
    }
}

// ---------------- TF32 mma.sync GEMM (R10-proven: 128x64, reg-staged, 2 CTA/SM) ----------------
#define TBM 128
#define TBN 64
#define TBK 32
#define ASTR 36
#define BSTR 68
#define ABUF (TBM*ASTR)            // 4608 floats
#define BBUF (TBK*BSTR)            // 2176 floats
#define TGEMM_SMEM ((2*ABUF + 2*BBUF) * 4)

template<int EPI, bool GATHER, int ROUND>
__global__ __launch_bounds__(256, 2) void tmma_k(
    const float* __restrict__ A, const float* __restrict__ B,
    const float* __restrict__ bias, const float* __restrict__ res,
    float* __restrict__ C, int M, int N, int Kd,
    const int* __restrict__ ridx, const int* __restrict__ mcnt)
{
    int Meff = mcnt ? *mcnt : M;
    int row0 = blockIdx.y * TBM;
    if (row0 >= Meff) return;
    int col0 = blockIdx.x * TBN;

    extern __shared__ float smem[];
    float* As = smem;              // [2][ABUF]
    float* Bs = smem + 2 * ABUF;   // [2][BBUF]

    int tid  = threadIdx.x;
    int wid  = tid >> 5;
    int lane = tid & 31;

    const float* arow[4];
    int ar = tid >> 3;
    int ac4 = tid & 7;
#pragma unroll
    for (int i = 0; i < 4; i++) {
        int gr = row0 + i * 32 + ar;
        int cr = gr < Meff ? gr : Meff - 1;
        int src = GATHER ? ridx[cr] : cr;
        arow[i] = A + (size_t)src * Kd + ac4 * 4;
    }
    const float* bptr = B + (size_t)ar * N + col0 + ac4 * 4;

    float4 aR[4]; float4 bR[2];
    auto gload = [&](int c) {
        int k0 = c * TBK;
#pragma unroll
        for (int i = 0; i < 4; i++) aR[i] = *(const float4*)(arow[i] + k0);
#pragma unroll
        for (int i = 0; i < 2; i++) bR[i] = *(const float4*)(bptr + (size_t)k0 * N + i * 32);
    };
    auto sstore = [&](int b) {
        float* Ab = As + b * ABUF;
        float* Bb = Bs + b * BBUF;
#pragma unroll
        for (int i = 0; i < 4; i++)
            *(float4*)(Ab + (i * 32 + ar) * ASTR + ac4 * 4) = aR[i];   // A pre-rounded
#pragma unroll
        for (int i = 0; i < 2; i++) {
            uint4 v = make_uint4(f2tf32(bR[i].x), f2tf32(bR[i].y),
                                 f2tf32(bR[i].z), f2tf32(bR[i].w));    // round weights here
            *(uint4*)(Bb + ar * BSTR + ac4 * 4 + i * 32) = v;
        }
    };

    int g = lane >> 2, t = lane & 3;
    int m0 = (wid & 3) * 32;
    int n0 = (wid >> 2) * 32;
    float acc[2][4][4];
#pragma unroll
    for (int mt = 0; mt < 2; mt++)
#pragma unroll
        for (int nt = 0; nt < 4; nt++)
#pragma unroll
            for (int i = 0; i < 4; i++) acc[mt][nt][i] = 0.f;

    auto compute = [&](int b) {
        const uint32_t* Ab = (const uint32_t*)(As + b * ABUF);
        const uint32_t* Bb = (const uint32_t*)(Bs + b * BBUF);
#pragma unroll
        for (int kk = 0; kk < TBK; kk += 8) {
            uint32_t af[2][4], bf[4][2];
#pragma unroll
            for (int mt = 0; mt < 2; mt++) {
                int base = (m0 + mt * 16 + g) * ASTR + kk + t;
                af[mt][0] = Ab[base];
                af[mt][1] = Ab[base + 8 * ASTR];
                af[mt][2] = Ab[base + 4];
                af[mt][3] = Ab[base + 8 * ASTR + 4];
            }
#pragma unroll
            for (int nt = 0; nt < 4; nt++) {
                int nb = n0 + nt * 8 + g;
                bf[nt][0] = Bb[(kk + t) * BSTR + nb];
                bf[nt][1] = Bb[(kk + t + 4) * BSTR + nb];
            }
#pragma unroll
            for (int mt = 0; mt < 2; mt++)
#pragma unroll
                for (int nt = 0; nt < 4; nt++)
                    mma_tf32(acc[mt][nt], af[mt], bf[nt]);
        }
    };

    const int NC = Kd / TBK;
    gload(0); sstore(0);
    __syncthreads();
    for (int c = 0; c < NC; c++) {
        if (c + 1 < NC) gload(c + 1);
        compute(c & 1);
        if (c + 1 < NC) sstore((c + 1) & 1);
        __syncthreads();
    }

#pragma unroll
    for (int mt = 0; mt < 2; mt++) {
#pragma unroll
        for (int hrow = 0; hrow < 2; hrow++) {
            int gr = row0 + m0 + mt * 16 + hrow * 8 + g;
            if (gr >= Meff) continue;
            float* crow = C + (size_t)gr * N;
            const float* rrow = (EPI == 1) ? (res + (size_t)gr * N) : nullptr;
#pragma unroll
            for (int nt = 0; nt < 4; nt++) {
                int gc = col0 + n0 + nt * 8 + 2 * t;
                float v0 = acc[mt][nt][hrow * 2 + 0] + bias[gc];
                float v1 = acc[mt][nt][hrow * 2 + 1] + bias[gc + 1];
                if (EPI == 1) { v0 += rrow[gc]; v1 += rrow[gc + 1]; }
                if (EPI == 2) { v0 = gelu_f(v0); v1 = gelu_f(v1); }
                if (ROUND)    { v0 = f2tf32f(v0); v1 = f2tf32f(v1); }
                *(float2*)(crow + gc) = make_float2(v0, v1);
            }
        }
    }
}

// ---------------- TF32 tensor-core causal flash attention ----------------
// 128 q-rows per CTA, 8 warps x 16 rows, 256 threads. K/V tiles of 64 shared by
// all warps (2x fewer loads/barriers vs 64-row CTAs). q/k/v arrive pre-rounded
// tf32 (GEMM ROUND=1 epilogue) -> plain float4 copies, no cvt in the loop.
// Ps aliases the dead Qs staging region.
#define QT 128
#define KT 64
#define KSTR 68
#define ATT_SMEM ((QT*KSTR + 2*KT*KSTR) * 4)   // 69632 bytes

__global__ __launch_bounds__(256) void attn_tc_k(
    const float* __restrict__ q, const float* __restrict__ k,
    const float* __restrict__ v, float* __restrict__ o)
{
    extern __shared__ float sm[];
    float* Qs = sm;                     // [128][KSTR], reused as Ps after extraction
    float* Ks = sm + QT * KSTR;         // [64][KSTR]
    float* Vs = sm + QT * KSTR + KT * KSTR;
    float* Ps = Qs;                     // [8][16][KSTR]

    int bh = blockIdx.y;
    int b = bh >> 4, h = bh & 15;
    int qb = blockIdx.x * QT;
    int tid = threadIdx.x, wid = tid >> 5, lane = tid & 31;
    int g = lane >> 2, t = lane & 3;
    size_t base = ((size_t)b * Sc) * Dc + h * DHc;

    // load Q tile (pre-rounded tf32; x0.125 exact in tf32)
#pragma unroll
    for (int i = 0; i < 8; i++) {
        int idx = tid + i * 256;
        int r = idx >> 4, c4 = (idx & 15) * 4;
        float4 val = *(const float4*)(q + base + (size_t)(qb + r) * Dc + c4);
        val.x *= 0.125f; val.y *= 0.125f; val.z *= 0.125f; val.w *= 0.125f;
        *(float4*)(Qs + r * KSTR + c4) = val;
    }
    __syncthreads();

    int qrow = wid * 16;
    uint32_t qf[8][4];
    {
        const uint32_t* Q32 = (const uint32_t*)Qs;
#pragma unroll
        for (int kc = 0; kc < 8; kc++) {
            int base0 = (qrow + g) * KSTR + kc * 8 + t;
            qf[kc][0] = Q32[base0];
            qf[kc][1] = Q32[base0 + 8 * KSTR];
            qf[kc][2] = Q32[base0 + 4];
            qf[kc][3] = Q32[base0 + 8 * KSTR + 4];
        }
    }
    __syncthreads();   // Qs dead; Ps may be written from here on

    float oa[8][4];
#pragma unroll
    for (int nt = 0; nt < 8; nt++)
#pragma unroll
        for (int i = 0; i < 4; i++) oa[nt][i] = 0.f;
    float m0 = -1e30f, m1 = -1e30f, l0 = 0.f, l1 = 0.f;
    int r0 = qb + qrow + g, r1 = r0 + 8;

    int ntiles = qb / KT + 2;
    float* Pw = Ps + wid * 16 * KSTR;
    uint32_t* Pw32 = (uint32_t*)Pw;
    const uint32_t* K32 = (const uint32_t*)Ks;
    const uint32_t* V32 = (const uint32_t*)Vs;

    for (int tile = 0; tile < ntiles; tile++) {
        int j0 = tile * KT;
        __syncthreads();   // previous-iter reads of Ks/Vs complete
        // load K/V tiles (pre-rounded tf32, straight copies)
#pragma unroll
        for (int i = 0; i < 4; i++) {
            int idx = tid + i * 256;
            int r = idx >> 4, c4 = (idx & 15) * 4;
            size_t goff = base + (size_t)(j0 + r) * Dc + c4;
            *(float4*)(Ks + r * KSTR + c4) = *(const float4*)(k + goff);
            *(float4*)(Vs + r * KSTR + c4) = *(const float4*)(v + goff);
        }
        __syncthreads();

        if (j0 > qb + qrow + 15) continue;   // fully masked for this warp (warp-uniform)

        float s[8][4];
#pragma unroll
        for (int nt = 0; nt < 8; nt++) {
            s[nt][0] = s[nt][1] = s[nt][2] = s[nt][3] = 0.f;
            const uint32_t* krow = K32 + (nt * 8 + g) * KSTR;
#pragma unroll
            for (int kc = 0; kc < 8; kc++) {
                uint32_t bf[2] = { krow[kc * 8 + t], krow[kc * 8 + t + 4] };
                mma_tf32(s[nt], qf[kc], bf);
            }
        }
        if (j0 + KT - 1 > qb + qrow) {       // diagonal tile for this warp
#pragma unroll
            for (int nt = 0; nt < 8; nt++) {
                int cbp = j0 + nt * 8 + 2 * t;
                if (cbp > r0)     s[nt][0] = -1e30f;
                if (cbp + 1 > r0) s[nt][1] = -1e30f;
                if (cbp > r1)     s[nt][2] = -1e30f;
                if (cbp + 1 > r1) s[nt][3] = -1e30f;
            }
        }
        float mt0 = -1e30f, mt1 = -1e30f;
#pragma unroll
        for (int nt = 0; nt < 8; nt++) {
            mt0 = fmaxf(mt0, fmaxf(s[nt][0], s[nt][1]));
            mt1 = fmaxf(mt1, fmaxf(s[nt][2], s[nt][3]));
        }
#pragma unroll
        for (int off = 1; off <= 2; off <<= 1) {
            mt0 = fmaxf(mt0, __shfl_xor_sync(0xffffffffu, mt0, off));
            mt1 = fmaxf(mt1, __shfl_xor_sync(0xffffffffu, mt1, off));
        }
        float mn0 = fmaxf(m0, mt0), mn1 = fmaxf(m1, mt1);
        float c0 = __expf(m0 - mn0), c1 = __expf(m1 - mn1);
        m0 = mn0; m1 = mn1;
        l0 *= c0; l1 *= c1;
#pragma unroll
        for (int nt = 0; nt < 8; nt++) {
            oa[nt][0] *= c0; oa[nt][1] *= c0;
            oa[nt][2] *= c1; oa[nt][3] *= c1;
        }
#pragma unroll
        for (int nt = 0; nt < 8; nt++) {
            float p0 = __expf(s[nt][0] - m0);
            float p1 = __expf(s[nt][1] - m0);
            float p2 = __expf(s[nt][2] - m1);
            float p3 = __expf(s[nt][3] - m1);
            l0 += p0 + p1; l1 += p2 + p3;
            int cbp = nt * 8 + 2 * t;
            *(uint2*)(Pw32 + g * KSTR + cbp)       = make_uint2(f2tf32(p0), f2tf32(p1));
            *(uint2*)(Pw32 + (g + 8) * KSTR + cbp) = make_uint2(f2tf32(p2), f2tf32(p3));
        }
        __syncwarp();
        uint32_t af[8][4];
#pragma unroll
        for (int kc = 0; kc < 8; kc++) {
            int base0 = g * KSTR + kc * 8 + t;
            af[kc][0] = Pw32[base0];
            af[kc][1] = Pw32[base0 + 8 * KSTR];
            af[kc][2] = Pw32[base0 + 4];
            af[kc][3] = Pw32[base0 + 8 * KSTR + 4];
        }
#pragma unroll
        for (int nt = 0; nt < 8; nt++) {
#pragma unroll
            for (int kc = 0; kc < 8; kc++) {
                uint32_t bf[2] = { V32[(kc * 8 + t) * KSTR + nt * 8 + g],
                                   V32[(kc * 8 + t + 4) * KSTR + nt * 8 + g] };
                mma_tf32(oa[nt], af[kc], bf);
            }
        }
        __syncwarp();
    }

#pragma unroll
    for (int off = 1; off <= 2; off <<= 1) {
        l0 += __shfl_xor_sync(0xffffffffu, l0, off);
        l1 += __shfl_xor_sync(0xffffffffu, l1, off);
    }
    float i0 = 1.f / l0, i1 = 1.f / l1;
    float* o0 = o + base + (size_t)r0 * Dc;
    float* o1 = o + base + (size_t)r1 * Dc;
#pragma unroll
    for (int nt = 0; nt < 8; nt++) {
        int cbp = nt * 8 + 2 * t;
        *(float2*)(o0 + cbp) = make_float2(f2tf32f(oa[nt][0] * i0), f2tf32f(oa[nt][1] * i0));
        *(float2*)(o1 + cbp) = make_float2(f2tf32f(oa[nt][2] * i1), f2tf32f(oa[nt][3] * i1));
    }
}

// ---------------- MoE routing (consumes fp32 ln2) ----------------
__global__ void route_k(const float* __restrict__ ln2,
                        const float* __restrict__ Wg, const float* __restrict__ bg) {
    int t = blockIdx.x;
    int tid = threadIdx.x;
    int w = tid >> 5, lane = tid & 31;
    const float* xr = ln2 + (size_t)t * Dc;
    float s = 0.f;
    for (int d = lane; d < Dc; d += 32) s += xr[d] * Wg[d * Ec + w];
#pragma unroll
    for (int off = 16; off > 0; off >>= 1) s += __shfl_down_sync(0xffffffffu, s, off);
    __shared__ float lg[Ec];
    if (lane == 0) lg[w] = s + bg[w];
    __syncthreads();
    if (tid == 0) {
        float mx = lg[0];
        for (int e = 1; e < Ec; e++) mx = fmaxf(mx, lg[e]);
        float p[Ec]; float sum = 0.f;
        for (int e = 0; e < Ec; e++) { p[e] = __expf(lg[e] - mx); sum += p[e]; }
        float inv = 1.f / sum;
        for (int e = 0; e < Ec; e++) { p[e] *= inv; atomicAdd(&g_pmean[e], p[e]); }
        int e0 = 0; for (int e = 1; e < Ec; e++) if (p[e] > p[e0]) e0 = e;
        int e1 = (e0 == 0) ? 1 : 0;
        for (int e = 0; e < Ec; e++) if (e != e0 && p[e] > p[e1]) e1 = e;
        float w0 = p[e0], w1 = p[e1], wn = 1.f / (w0 + w1);
        w0 *= wn; w1 *= wn;
        int s0 = atomicAdd(&g_cnt[e0], 1);
        int s1 = atomicAdd(&g_cnt[e1], 1);
        g_list[e0 * Tc + s0] = t; g_list[e1 * Tc + s1] = t;
        g_te[2*t] = e0; g_te[2*t+1] = e1;
        g_pos[2*t] = s0; g_pos[2*t+1] = s1;
        g_tw[2*t] = w0; g_tw[2*t+1] = w1;
    }
}

// ---------------- combine & aux ----------------
__global__ void combine_k(float* __restrict__ out) {
    int t = blockIdx.x;
    int e0 = g_te[2*t], e1 = g_te[2*t+1];
    int s0 = g_pos[2*t], s1 = g_pos[2*t+1];
    float w0 = g_tw[2*t], w1 = g_tw[2*t+1];
    const float* y0 = g_y + ((size_t)e0 * Tc + s0) * Dc;
    const float* y1 = g_y + ((size_t)e1 * Tc + s1) * Dc;
    const float* r  = g_res1 + (size_t)t * Dc;
    float* o = out + (size_t)t * Dc;
    for (int d = threadIdx.x; d < Dc; d += 256)
        o[d] = r[d] + w0 * y0[d] + w1 * y1[d];
}

__global__ void aux_k(float* __restrict__ out) {
    if (threadIdx.x == 0) {
        float a = 0.f;
        for (int e = 0; e < Ec; e++) a += (float)g_cnt[e] * g_pmean[e];
        out[0] = 0.01f * (float)Ec * a / ((float)Tc * (float)Tc);
    }
}

// ---------------- launch ----------------
extern "C" void kernel_launch(void* const* d_in, const int* in_sizes, int n_in,
                              void* d_out, int out_size) {
    (void)in_sizes; (void)n_in;
    const float* x   = (const float*)d_in[0];
    const float* l1s = (const float*)d_in[1];
    const float* l1b = (const float*)d_in[2];
    const float* Wq  = (const float*)d_in[3];
    const float* bq  = (const float*)d_in[4];
    const float* Wk  = (const float*)d_in[5];
    const float* bk  = (const float*)d_in[6];
    const float* Wv  = (const float*)d_in[7];
    const float* bv  = (const float*)d_in[8];
    const float* Wo  = (const float*)d_in[9];
    const float* bo  = (const float*)d_in[10];
    const float* l2s = (const float*)d_in[11];
    const float* l2b = (const float*)d_in[12];
    const float* Wg  = (const float*)d_in[13];
    const float* bg  = (const float*)d_in[14];
    const float* W1  = (const float*)d_in[15];
    const float* b1  = (const float*)d_in[16];
    const float* W2  = (const float*)d_in[17];
    const float* b2  = (const float*)d_in[18];
    float* out = (float*)d_out;

    float *ln1, *qb_, *kb_, *vb_, *attn, *res1, *ln2, *ln2r, *hb, *yb;
    int *lst, *cnt;
    cudaGetSymbolAddress((void**)&ln1,  g_ln1);
    cudaGetSymbolAddress((void**)&qb_,  g_q);
    cudaGetSymbolAddress((void**)&kb_,  g_k);
    cudaGetSymbolAddress((void**)&vb_,  g_v);
    cudaGetSymbolAddress((void**)&attn, g_attn);
    cudaGetSymbolAddress((void**)&res1, g_res1);
    cudaGetSymbolAddress((void**)&ln2,  g_ln2);
    cudaGetSymbolAddress((void**)&ln2r, g_ln2r);
    cudaGetSymbolAddress((void**)&hb,   g_h);
    cudaGetSymbolAddress((void**)&yb,   g_y);
    cudaGetSymbolAddress((void**)&lst,  g_list);
    cudaGetSymbolAddress((void**)&cnt,  g_cnt);

    cudaFuncSetAttribute((const void*)tmma_k<0,false,1>, cudaFuncAttributeMaxDynamicSharedMemorySize, TGEMM_SMEM);
    cudaFuncSetAttribute((const void*)tmma_k<1,false,0>, cudaFuncAttributeMaxDynamicSharedMemorySize, TGEMM_SMEM);
    cudaFuncSetAttribute((const void*)tmma_k<0,false,0>, cudaFuncAttributeMaxDynamicSharedMemorySize, TGEMM_SMEM);
    cudaFuncSetAttribute((const void*)tmma_k<2,true,1>,  cudaFuncAttributeMaxDynamicSharedMemorySize, TGEMM_SMEM);
    cudaFuncSetAttribute((const void*)attn_tc_k,         cudaFuncAttributeMaxDynamicSharedMemorySize, ATT_SMEM);

    init_k<<<1, 32>>>();
    ln_k<false><<<Tc, 256>>>(x, l1s, l1b, ln1, nullptr);

    dim3 gD(Dc / TBN, Tc / TBM);   // (16, 32)
    tmma_k<0,false,1><<<gD, 256, TGEMM_SMEM>>>(ln1, Wq, bq, nullptr, qb_, Tc, Dc, Dc, nullptr, nullptr);
    tmma_k<0,false,1><<<gD, 256, TGEMM_SMEM>>>(ln1, Wk, bk, nullptr, kb_, Tc, Dc, Dc, nullptr, nullptr);
    tmma_k<0,false,1><<<gD, 256, TGEMM_SMEM>>>(ln1, Wv, bv, nullptr, vb_, Tc, Dc, Dc, nullptr, nullptr);

    attn_tc_k<<<dim3(Sc / QT, Bc * Hc), 256, ATT_SMEM>>>(qb_, kb_, vb_, attn);

    tmma_k<1,false,0><<<gD, 256, TGEMM_SMEM>>>(attn, Wo, bo, x, res1, Tc, Dc, Dc, nullptr, nullptr);
    ln_k<true><<<Tc, 256>>>(res1, l2s, l2b, ln2, ln2r);   // fp32 for routing, rounded for GEMM
    route_k<<<Tc, 256>>>(ln2, Wg, bg);

    dim3 gF(FHc / TBN, Tc / TBM);  // (64, 32)
    for (int e = 0; e < Ec; e++) {
        tmma_k<2,true,1><<<gF, 256, TGEMM_SMEM>>>(ln2r, W1 + (size_t)e * Dc * FHc,
                                                  b1 + (size_t)e * FHc, nullptr, hb,
                                                  Tc, FHc, Dc, lst + e * Tc, cnt + e);
        tmma_k<0,false,0><<<gD, 256, TGEMM_SMEM>>>(hb, W2 + (size_t)e * FHc * Dc,
                                                   b2 + (size_t)e * Dc, nullptr,
                                                   yb + (size_t)e * Tc * Dc,
                                                   Tc, Dc, FHc, nullptr, cnt + e);
    }

    combine_k<<<Tc, 256>>>(out);
    if (out_size > Tc * Dc) aux_k<<<1, 32>>>(out + (size_t)Tc * Dc);
}

// round 16
// speedup vs baseline: 1.8201x; 1.3820x over previous
#include <cuda_runtime.h>
#include <math.h>
#include <stdint.h>

#define Bc 2
#define Sc 2048
#define Dc 1024
#define Hc 16
#define DHc 64
#define Ec 8
#define FHc 4096
#define Tc (Bc*Sc)   // 4096 tokens

// ---------------- scratch (device globals; no allocations) ----------------
__device__ float g_ln1[Tc*Dc];
__device__ float g_q[Tc*Dc];
__device__ float g_k[Tc*Dc];
__device__ float g_v[Tc*Dc];
__device__ float g_attn[Tc*Dc];
__device__ float g_res1[Tc*Dc];
__device__ float g_ln2[Tc*Dc];       // fp32 (for routing)
__device__ float g_ln2r[Tc*Dc];      // tf32-rounded (GEMM A operand)
__device__ float g_h[(size_t)Ec*Tc*FHc];   // per-expert hidden (512 MB)
__device__ float g_y[(size_t)Ec*Tc*Dc];
__device__ int   g_cnt[Ec];
__device__ float g_pmean[Ec];
__device__ int   g_list[Ec*Tc];
__device__ int   g_te[2*Tc];
__device__ int   g_pos[2*Tc];
__device__ float g_tw[2*Tc];

__global__ void init_k() {
    int i = threadIdx.x;
    if (i < Ec) { g_cnt[i] = 0; g_pmean[i] = 0.f; }
}

// ---------------- helpers ----------------
__device__ __forceinline__ uint32_t f2tf32(float x) {
    uint32_t r;
    asm("cvt.rna.tf32.f32 %0, %1;" : "=r"(r) : "f"(x));
    return r;
}
__device__ __forceinline__ float f2tf32f(float x) {
    return __uint_as_float(f2tf32(x));
}
__device__ __forceinline__ void mma_tf32(float* c, const uint32_t* a, const uint32_t* b) {
    asm volatile(
        "mma.sync.aligned.m16n8k8.row.col.f32.tf32.tf32.f32 "
        "{%0,%1,%2,%3}, {%4,%5,%6,%7}, {%8,%9}, {%0,%1,%2,%3};"
        : "+f"(c[0]), "+f"(c[1]), "+f"(c[2]), "+f"(c[3])
        : "r"(a[0]), "r"(a[1]), "r"(a[2]), "r"(a[3]), "r"(b[0]), "r"(b[1]));
}
__device__ __forceinline__ float gelu_f(float x) {
    float x3 = x * x * x;
    float t = tanhf(0.7978845608028654f * (x + 0.044715f * x3));
    return 0.5f * x * (1.0f + t);
}

// ---------------- LayerNorm ----------------
template<bool DUAL>
__global__ void ln_k(const float* __restrict__ in, const float* __restrict__ sc,
                     const float* __restrict__ bi, float* __restrict__ out,
                     float* __restrict__ out2) {
    __shared__ float xs[Dc];
    __shared__ float red[256];
    int t = blockIdx.x, tid = threadIdx.x;
    const float* r = in + (size_t)t * Dc;
    float s = 0.f;
    for (int d = tid; d < Dc; d += 256) { float v = r[d]; xs[d] = v; s += v; }
    red[tid] = s; __syncthreads();
    for (int o = 128; o > 0; o >>= 1) { if (tid < o) red[tid] += red[tid + o]; __syncthreads(); }
    float mu = red[0] * (1.0f / Dc);
    __syncthreads();
    float s2 = 0.f;
    for (int d = tid; d < Dc; d += 256) { float dv = xs[d] - mu; s2 += dv * dv; }
    red[tid] = s2; __syncthreads();
    for (int o = 128; o > 0; o >>= 1) { if (tid < o) red[tid] += red[tid + o]; __syncthreads(); }
    float inv = rsqrtf(red[0] * (1.0f / Dc) + 1e-6f);
    float* orow = out + (size_t)t * Dc;
    float* orow2 = DUAL ? (out2 + (size_t)t * Dc) : nullptr;
    for (int d = tid; d < Dc; d += 256) {
        float v = (xs[d] - mu) * inv * sc[d] + bi[d];
        if (DUAL) { orow[d] = v; orow2[d] = f2tf32f(v); }
        else      { orow[d] = f2tf32f(v); }
    }
}

// ---------------- TF32 mma.sync GEMM (R10 data path + blockIdx.z expert batching) --
// A pre-rounded tf32; B (weights) rounded on the fly. mcnt is indexed by blockIdx.z.
// EPI: 0 bias; 1 bias+res; 2 bias+gelu. ROUND: round C store to tf32.
#define TBM 128
#define TBN 64
#define TBK 32
#define ASTR 36
#define BSTR 68
#define ABUF (TBM*ASTR)            // 4608 floats
#define BBUF (TBK*BSTR)            // 2176 floats
#define TGEMM_SMEM ((2*ABUF + 2*BBUF) * 4)

template<int EPI, bool GATHER, int ROUND>
__global__ __launch_bounds__(256, 2) void tmma_k(
    const float* __restrict__ A, const float* __restrict__ B,
    const float* __restrict__ bias, const float* __restrict__ res,
    float* __restrict__ C, int M, int N, int Kd,
    const int* __restrict__ ridx, const int* __restrict__ mcnt,
    size_t aStrideZ, size_t bStrideZ, int biasStrideZ, size_t cStrideZ, int ridxStrideZ)
{
    int ez = blockIdx.z;
    A    += (size_t)ez * aStrideZ;
    B    += (size_t)ez * bStrideZ;
    bias += (size_t)ez * biasStrideZ;
    C    += (size_t)ez * cStrideZ;
    if (GATHER) ridx += (size_t)ez * ridxStrideZ;

    int Meff = mcnt ? mcnt[ez] : M;
    int row0 = blockIdx.y * TBM;
    if (row0 >= Meff) return;
    int col0 = blockIdx.x * TBN;

    extern __shared__ float smem[];
    float* As = smem;              // [2][ABUF]
    float* Bs = smem + 2 * ABUF;   // [2][BBUF]

    int tid  = threadIdx.x;
    int wid  = tid >> 5;
    int lane = tid & 31;

    const float* arow[4];
    int ar = tid >> 3;
    int ac4 = tid & 7;
#pragma unroll
    for (int i = 0; i < 4; i++) {
        int gr = row0 + i * 32 + ar;
        int cr = gr < Meff ? gr : Meff - 1;
        int src = GATHER ? ridx[cr] : cr;
        arow[i] = A + (size_t)src * Kd + ac4 * 4;
    }
    const float* bptr = B + (size_t)ar * N + col0 + ac4 * 4;

    float4 aR[4]; float4 bR[2];
    auto gload = [&](int c) {
        int k0 = c * TBK;
#pragma unroll
        for (int i = 0; i < 4; i++) aR[i] = *(const float4*)(arow[i] + k0);
#pragma unroll
        for (int i = 0; i < 2; i++) bR[i] = *(const float4*)(bptr + (size_t)k0 * N + i * 32);
    };
    auto sstore = [&](int b) {
        float* Ab = As + b * ABUF;
        float* Bb = Bs + b * BBUF;
#pragma unroll
        for (int i = 0; i < 4; i++)
            *(float4*)(Ab + (i * 32 + ar) * ASTR + ac4 * 4) = aR[i];   // A pre-rounded
#pragma unroll
        for (int i = 0; i < 2; i++) {
            uint4 v = make_uint4(f2tf32(bR[i].x), f2tf32(bR[i].y),
                                 f2tf32(bR[i].z), f2tf32(bR[i].w));    // round weights here
            *(uint4*)(Bb + ar * BSTR + ac4 * 4 + i * 32) = v;
        }
    };

    int g = lane >> 2, t = lane & 3;
    int m0 = (wid & 3) * 32;
    int n0 = (wid >> 2) * 32;
    float acc[2][4][4];
#pragma unroll
    for (int mt = 0; mt < 2; mt++)
#pragma unroll
        for (int nt = 0; nt < 4; nt++)
#pragma unroll
            for (int i = 0; i < 4; i++) acc[mt][nt][i] = 0.f;

    auto compute = [&](int b) {
        const uint32_t* Ab = (const uint32_t*)(As + b * ABUF);
        const uint32_t* Bb = (const uint32_t*)(Bs + b * BBUF);
#pragma unroll
        for (int kk = 0; kk < TBK; kk += 8) {
            uint32_t af[2][4], bf[4][2];
#pragma unroll
            for (int mt = 0; mt < 2; mt++) {
                int base = (m0 + mt * 16 + g) * ASTR + kk + t;
                af[mt][0] = Ab[base];
                af[mt][1] = Ab[base + 8 * ASTR];
                af[mt][2] = Ab[base + 4];
                af[mt][3] = Ab[base + 8 * ASTR + 4];
            }
#pragma unroll
            for (int nt = 0; nt < 4; nt++) {
                int nb = n0 + nt * 8 + g;
                bf[nt][0] = Bb[(kk + t) * BSTR + nb];
                bf[nt][1] = Bb[(kk + t + 4) * BSTR + nb];
            }
#pragma unroll
            for (int mt = 0; mt < 2; mt++)
#pragma unroll
                for (int nt = 0; nt < 4; nt++)
                    mma_tf32(acc[mt][nt], af[mt], bf[nt]);
        }
    };

    const int NC = Kd / TBK;
    gload(0); sstore(0);
    __syncthreads();
    for (int c = 0; c < NC; c++) {
        if (c + 1 < NC) gload(c + 1);
        compute(c & 1);
        if (c + 1 < NC) sstore((c + 1) & 1);
        __syncthreads();
    }

#pragma unroll
    for (int mt = 0; mt < 2; mt++) {
#pragma unroll
        for (int hrow = 0; hrow < 2; hrow++) {
            int gr = row0 + m0 + mt * 16 + hrow * 8 + g;
            if (gr >= Meff) continue;
            float* crow = C + (size_t)gr * N;
            const float* rrow = (EPI == 1) ? (res + (size_t)gr * N) : nullptr;
#pragma unroll
            for (int nt = 0; nt < 4; nt++) {
                int gc = col0 + n0 + nt * 8 + 2 * t;
                float v0 = acc[mt][nt][hrow * 2 + 0] + bias[gc];
                float v1 = acc[mt][nt][hrow * 2 + 1] + bias[gc + 1];
                if (EPI == 1) { v0 += rrow[gc]; v1 += rrow[gc + 1]; }
                if (EPI == 2) { v0 = gelu_f(v0); v1 = gelu_f(v1); }
                if (ROUND)    { v0 = f2tf32f(v0); v1 = f2tf32f(v1); }
                *(float2*)(crow + gc) = make_float2(v0, v1);
            }
        }
    }
}

// ---------------- TF32 tensor-core causal flash attention (R12 version) ----------------
#define QT 128
#define KT 64
#define KSTR 68
#define ATT_SMEM ((QT*KSTR + 2*KT*KSTR) * 4)

__global__ __launch_bounds__(256) void attn_tc_k(
    const float* __restrict__ q, const float* __restrict__ k,
    const float* __restrict__ v, float* __restrict__ o)
{
    extern __shared__ float sm[];
    float* Qs = sm;
    float* Ks = sm + QT * KSTR;
    float* Vs = sm + QT * KSTR + KT * KSTR;
    float* Ps = Qs;

    int bh = blockIdx.y;
    int b = bh >> 4, h = bh & 15;
    int qb = blockIdx.x * QT;
    int tid = threadIdx.x, wid = tid >> 5, lane = tid & 31;
    int g = lane >> 2, t = lane & 3;
    size_t base = ((size_t)b * Sc) * Dc + h * DHc;

#pragma unroll
    for (int i = 0; i < 8; i++) {
        int idx = tid + i * 256;
        int r = idx >> 4, c4 = (idx & 15) * 4;
        float4 val = *(const float4*)(q + base + (size_t)(qb + r) * Dc + c4);
        val.x *= 0.125f; val.y *= 0.125f; val.z *= 0.125f; val.w *= 0.125f;
        *(float4*)(Qs + r * KSTR + c4) = val;
    }
    __syncthreads();

    int qrow = wid * 16;
    uint32_t qf[8][4];
    {
        const uint32_t* Q32 = (const uint32_t*)Qs;
#pragma unroll
        for (int kc = 0; kc < 8; kc++) {
            int base0 = (qrow + g) * KSTR + kc * 8 + t;
            qf[kc][0] = Q32[base0];
            qf[kc][1] = Q32[base0 + 8 * KSTR];
            qf[kc][2] = Q32[base0 + 4];
            qf[kc][3] = Q32[base0 + 8 * KSTR + 4];
        }
    }
    __syncthreads();

    float oa[8][4];
#pragma unroll
    for (int nt = 0; nt < 8; nt++)
#pragma unroll
        for (int i = 0; i < 4; i++) oa[nt][i] = 0.f;
    float m0 = -1e30f, m1 = -1e30f, l0 = 0.f, l1 = 0.f;
    int r0 = qb + qrow + g, r1 = r0 + 8;

    int ntiles = qb / KT + 2;
    float* Pw = Ps + wid * 16 * KSTR;
    uint32_t* Pw32 = (uint32_t*)Pw;
    const uint32_t* K32 = (const uint32_t*)Ks;
    const uint32_t* V32 = (const uint32_t*)Vs;

    for (int tile = 0; tile < ntiles; tile++) {
        int j0 = tile * KT;
        __syncthreads();
#pragma unroll
        for (int i = 0; i < 4; i++) {
            int idx = tid + i * 256;
            int r = idx >> 4, c4 = (idx & 15) * 4;
            size_t goff = base + (size_t)(j0 + r) * Dc + c4;
            *(float4*)(Ks + r * KSTR + c4) = *(const float4*)(k + goff);
            *(float4*)(Vs + r * KSTR + c4) = *(const float4*)(v + goff);
        }
        __syncthreads();

        if (j0 > qb + qrow + 15) continue;

        float s[8][4];
#pragma unroll
        for (int nt = 0; nt < 8; nt++) {
            s[nt][0] = s[nt][1] = s[nt][2] = s[nt][3] = 0.f;
            const uint32_t* krow = K32 + (nt * 8 + g) * KSTR;
#pragma unroll
            for (int kc = 0; kc < 8; kc++) {
                uint32_t bf[2] = { krow[kc * 8 + t], krow[kc * 8 + t + 4] };
                mma_tf32(s[nt], qf[kc], bf);
            }
        }
        if (j0 + KT - 1 > qb + qrow) {
#pragma unroll
            for (int nt = 0; nt < 8; nt++) {
                int cbp = j0 + nt * 8 + 2 * t;
                if (cbp > r0)     s[nt][0] = -1e30f;
                if (cbp + 1 > r0) s[nt][1] = -1e30f;
                if (cbp > r1)     s[nt][2] = -1e30f;
                if (cbp + 1 > r1) s[nt][3] = -1e30f;
            }
        }
        float mt0 = -1e30f, mt1 = -1e30f;
#pragma unroll
        for (int nt = 0; nt < 8; nt++) {
            mt0 = fmaxf(mt0, fmaxf(s[nt][0], s[nt][1]));
            mt1 = fmaxf(mt1, fmaxf(s[nt][2], s[nt][3]));
        }
#pragma unroll
        for (int off = 1; off <= 2; off <<= 1) {
            mt0 = fmaxf(mt0, __shfl_xor_sync(0xffffffffu, mt0, off));
            mt1 = fmaxf(mt1, __shfl_xor_sync(0xffffffffu, mt1, off));
        }
        float mn0 = fmaxf(m0, mt0), mn1 = fmaxf(m1, mt1);
        float c0 = __expf(m0 - mn0), c1 = __expf(m1 - mn1);
        m0 = mn0; m1 = mn1;
        l0 *= c0; l1 *= c1;
#pragma unroll
        for (int nt = 0; nt < 8; nt++) {
            oa[nt][0] *= c0; oa[nt][1] *= c0;
            oa[nt][2] *= c1; oa[nt][3] *= c1;
        }
#pragma unroll
        for (int nt = 0; nt < 8; nt++) {
            float p0 = __expf(s[nt][0] - m0);
            float p1 = __expf(s[nt][1] - m0);
            float p2 = __expf(s[nt][2] - m1);
            float p3 = __expf(s[nt][3] - m1);
            l0 += p0 + p1; l1 += p2 + p3;
            int cbp = nt * 8 + 2 * t;
            *(uint2*)(Pw32 + g * KSTR + cbp)       = make_uint2(f2tf32(p0), f2tf32(p1));
            *(uint2*)(Pw32 + (g + 8) * KSTR + cbp) = make_uint2(f2tf32(p2), f2tf32(p3));
        }
        __syncwarp();
        uint32_t af[8][4];
#pragma unroll
        for (int kc = 0; kc < 8; kc++) {
            int base0 = g * KSTR + kc * 8 + t;
            af[kc][0] = Pw32[base0];
            af[kc][1] = Pw32[base0 + 8 * KSTR];
            af[kc][2] = Pw32[base0 + 4];
            af[kc][3] = Pw32[base0 + 8 * KSTR + 4];
        }
#pragma unroll
        for (int nt = 0; nt < 8; nt++) {
#pragma unroll
            for (int kc = 0; kc < 8; kc++) {
                uint32_t bf[2] = { V32[(kc * 8 + t) * KSTR + nt * 8 + g],
                                   V32[(kc * 8 + t + 4) * KSTR + nt * 8 + g] };
                mma_tf32(oa[nt], af[kc], bf);
            }
        }
        __syncwarp();
    }

#pragma unroll
    for (int off = 1; off <= 2; off <<= 1) {
        l0 += __shfl_xor_sync(0xffffffffu, l0, off);
        l1 += __shfl_xor_sync(0xffffffffu, l1, off);
    }
    float i0 = 1.f / l0, i1 = 1.f / l1;
    float* o0 = o + base + (size_t)r0 * Dc;
    float* o1 = o + base + (size_t)r1 * Dc;
#pragma unroll
    for (int nt = 0; nt < 8; nt++) {
        int cbp = nt * 8 + 2 * t;
        *(float2*)(o0 + cbp) = make_float2(f2tf32f(oa[nt][0] * i0), f2tf32f(oa[nt][1] * i0));
        *(float2*)(o1 + cbp) = make_float2(f2tf32f(oa[nt][2] * i1), f2tf32f(oa[nt][3] * i1));
    }
}

// ---------------- MoE routing (consumes fp32 ln2) ----------------
__global__ void route_k(const float* __restrict__ ln2,
                        const float* __restrict__ Wg, const float* __restrict__ bg) {
    int t = blockIdx.x;
    int tid = threadIdx.x;
    int w = tid >> 5, lane = tid & 31;
    const float* xr = ln2 + (size_t)t * Dc;
    float s = 0.f;
    for (int d = lane; d < Dc; d += 32) s += xr[d] * Wg[d * Ec + w];
#pragma unroll
    for (int off = 16; off > 0; off >>= 1) s += __shfl_down_sync(0xffffffffu, s, off);
    __shared__ float lg[Ec];
    if (lane == 0) lg[w] = s + bg[w];
    __syncthreads();
    if (tid == 0) {
        float mx = lg[0];
        for (int e = 1; e < Ec; e++) mx = fmaxf(mx, lg[e]);
        float p[Ec]; float sum = 0.f;
        for (int e = 0; e < Ec; e++) { p[e] = __expf(lg[e] - mx); sum += p[e]; }
        float inv = 1.f / sum;
        for (int e = 0; e < Ec; e++) { p[e] *= inv; atomicAdd(&g_pmean[e], p[e]); }
        int e0 = 0; for (int e = 1; e < Ec; e++) if (p[e] > p[e0]) e0 = e;
        int e1 = (e0 == 0) ? 1 : 0;
        for (int e = 0; e < Ec; e++) if (e != e0 && p[e] > p[e1]) e1 = e;
        float w0 = p[e0], w1 = p[e1], wn = 1.f / (w0 + w1);
        w0 *= wn; w1 *= wn;
        int s0 = atomicAdd(&g_cnt[e0], 1);
        int s1 = atomicAdd(&g_cnt[e1], 1);
        g_list[e0 * Tc + s0] = t; g_list[e1 * Tc + s1] = t;
        g_te[2*t] = e0; g_te[2*t+1] = e1;
        g_pos[2*t] = s0; g_pos[2*t+1] = s1;
        g_tw[2*t] = w0; g_tw[2*t+1] = w1;
    }
}

// ---------------- combine & aux ----------------
__global__ void combine_k(float* __restrict__ out) {
    int t = blockIdx.x;
    int e0 = g_te[2*t], e1 = g_te[2*t+1];
    int s0 = g_pos[2*t], s1 = g_pos[2*t+1];
    float w0 = g_tw[2*t], w1 = g_tw[2*t+1];
    const float* y0 = g_y + ((size_t)e0 * Tc + s0) * Dc;
    const float* y1 = g_y + ((size_t)e1 * Tc + s1) * Dc;
    const float* r  = g_res1 + (size_t)t * Dc;
    float* o = out + (size_t)t * Dc;
    for (int d = threadIdx.x; d < Dc; d += 256)
        o[d] = r[d] + w0 * y0[d] + w1 * y1[d];
}

__global__ void aux_k(float* __restrict__ out) {
    if (threadIdx.x == 0) {
        float a = 0.f;
        for (int e = 0; e < Ec; e++) a += (float)g_cnt[e] * g_pmean[e];
        out[0] = 0.01f * (float)Ec * a / ((float)Tc * (float)Tc);
    }
}

// ---------------- launch ----------------
extern "C" void kernel_launch(void* const* d_in, const int* in_sizes, int n_in,
                              void* d_out, int out_size) {
    (void)in_sizes; (void)n_in;
    const float* x   = (const float*)d_in[0];
    const float* l1s = (const float*)d_in[1];
    const float* l1b = (const float*)d_in[2];
    const float* Wq  = (const float*)d_in[3];
    const float* bq  = (const float*)d_in[4];
    const float* Wk  = (const float*)d_in[5];
    const float* bk  = (const float*)d_in[6];
    const float* Wv  = (const float*)d_in[7];
    const float* bv  = (const float*)d_in[8];
    const float* Wo  = (const float*)d_in[9];
    const float* bo  = (const float*)d_in[10];
    const float* l2s = (const float*)d_in[11];
    const float* l2b = (const float*)d_in[12];
    const float* Wg  = (const float*)d_in[13];
    const float* bg  = (const float*)d_in[14];
    const float* W1  = (const float*)d_in[15];
    const float* b1  = (const float*)d_in[16];
    const float* W2  = (const float*)d_in[17];
    const float* b2  = (const float*)d_in[18];
    float* out = (float*)d_out;

    float *ln1, *qb_, *kb_, *vb_, *attn, *res1, *ln2, *ln2r, *hb, *yb;
    int *lst, *cnt;
    cudaGetSymbolAddress((void**)&ln1,  g_ln1);
    cudaGetSymbolAddress((void**)&qb_,  g_q);
    cudaGetSymbolAddress((void**)&kb_,  g_k);
    cudaGetSymbolAddress((void**)&vb_,  g_v);
    cudaGetSymbolAddress((void**)&attn, g_attn);
    cudaGetSymbolAddress((void**)&res1, g_res1);
    cudaGetSymbolAddress((void**)&ln2,  g_ln2);
    cudaGetSymbolAddress((void**)&ln2r, g_ln2r);
    cudaGetSymbolAddress((void**)&hb,   g_h);
    cudaGetSymbolAddress((void**)&yb,   g_y);
    cudaGetSymbolAddress((void**)&lst,  g_list);
    cudaGetSymbolAddress((void**)&cnt,  g_cnt);

    cudaFuncSetAttribute((const void*)tmma_k<0,false,1>, cudaFuncAttributeMaxDynamicSharedMemorySize, TGEMM_SMEM);
    cudaFuncSetAttribute((const void*)tmma_k<1,false,0>, cudaFuncAttributeMaxDynamicSharedMemorySize, TGEMM_SMEM);
    cudaFuncSetAttribute((const void*)tmma_k<0,false,0>, cudaFuncAttributeMaxDynamicSharedMemorySize, TGEMM_SMEM);
    cudaFuncSetAttribute((const void*)tmma_k<2,true,1>,  cudaFuncAttributeMaxDynamicSharedMemorySize, TGEMM_SMEM);
    cudaFuncSetAttribute((const void*)attn_tc_k,         cudaFuncAttributeMaxDynamicSharedMemorySize, ATT_SMEM);

    init_k<<<1, 32>>>();
    ln_k<false><<<Tc, 256>>>(x, l1s, l1b, ln1, nullptr);

    dim3 gD(Dc / TBN, Tc / TBM);   // (16, 32)
    tmma_k<0,false,1><<<gD, 256, TGEMM_SMEM>>>(ln1, Wq, bq, nullptr, qb_, Tc, Dc, Dc,
                                               nullptr, nullptr, 0, 0, 0, 0, 0);
    tmma_k<0,false,1><<<gD, 256, TGEMM_SMEM>>>(ln1, Wk, bk, nullptr, kb_, Tc, Dc, Dc,
                                               nullptr, nullptr, 0, 0, 0, 0, 0);
    tmma_k<0,false,1><<<gD, 256, TGEMM_SMEM>>>(ln1, Wv, bv, nullptr, vb_, Tc, Dc, Dc,
                                               nullptr, nullptr, 0, 0, 0, 0, 0);

    attn_tc_k<<<dim3(Sc / QT, Bc * Hc), 256, ATT_SMEM>>>(qb_, kb_, vb_, attn);

    tmma_k<1,false,0><<<gD, 256, TGEMM_SMEM>>>(attn, Wo, bo, x, res1, Tc, Dc, Dc,
                                               nullptr, nullptr, 0, 0, 0, 0, 0);
    ln_k<true><<<Tc, 256>>>(res1, l2s, l2b, ln2, ln2r);
    route_k<<<Tc, 256>>>(ln2, Wg, bg);

    // ---- MoE: ALL experts in 2 launches via blockIdx.z ----
    dim3 gW1(FHc / TBN, Tc / TBM, Ec);   // (64, 32, 8)
    tmma_k<2,true,1><<<gW1, 256, TGEMM_SMEM>>>(
        ln2r, W1, b1, nullptr, hb, Tc, FHc, Dc,
        lst, cnt,
        /*aStrideZ*/0, /*bStrideZ*/(size_t)Dc * FHc, /*biasStrideZ*/FHc,
        /*cStrideZ*/(size_t)Tc * FHc, /*ridxStrideZ*/Tc);

    dim3 gW2(Dc / TBN, Tc / TBM, Ec);    // (16, 32, 8)
    tmma_k<0,false,0><<<gW2, 256, TGEMM_SMEM>>>(
        hb, W2, b2, nullptr, yb, Tc, Dc, FHc,
        nullptr, cnt,
        /*aStrideZ*/(size_t)Tc * FHc, /*bStrideZ*/(size_t)FHc * Dc, /*biasStrideZ*/Dc,
        /*cStrideZ*/(size_t)Tc * Dc, /*ridxStrideZ*/0);

    combine_k<<<Tc, 256>>>(out);
    if (out_size > Tc * Dc) aux_k<<<1, 32>>>(out + (size_t)Tc * Dc);
}

// round 17
// speedup vs baseline: 2.4424x; 1.3419x over previous
#include <cuda_runtime.h>
#include <cuda_fp16.h>
#include <math.h>
#include <stdint.h>

#define Bc 2
#define Sc 2048
#define Dc 1024
#define Hc 16
#define DHc 64
#define Ec 8
#define FHc 4096
#define Tc (Bc*Sc)   // 4096 tokens

// ---------------- scratch (device globals; no allocations) ----------------
__device__ float g_ln1[Tc*Dc];
__device__ float g_q[Tc*Dc];
__device__ float g_k[Tc*Dc];
__device__ float g_v[Tc*Dc];
__device__ float g_attn[Tc*Dc];
__device__ float g_res1[Tc*Dc];
__device__ float g_ln2[Tc*Dc];             // fp32 (routing + W1 input)
__device__ float g_h[(size_t)Ec*Tc*FHc];   // per-expert hidden
__device__ float g_y[(size_t)Ec*Tc*Dc];
__device__ int   g_cnt[Ec];
__device__ float g_pmean[Ec];
__device__ int   g_list[Ec*Tc];
__device__ int   g_te[2*Tc];
__device__ int   g_pos[2*Tc];
__device__ float g_tw[2*Tc];

__global__ void init_k() {
    int i = threadIdx.x;
    if (i < Ec) { g_cnt[i] = 0; g_pmean[i] = 0.f; }
}

// ---------------- helpers ----------------
__device__ __forceinline__ uint32_t f2tf32(float x) {
    uint32_t r;
    asm("cvt.rna.tf32.f32 %0, %1;" : "=r"(r) : "f"(x));
    return r;
}
__device__ __forceinline__ float f2tf32f(float x) {
    return __uint_as_float(f2tf32(x));
}
__device__ __forceinline__ uint32_t f2h2(float lo, float hi) {
    __half2 h = __halves2half2(__float2half_rn(lo), __float2half_rn(hi));
    return *(uint32_t*)&h;
}
__device__ __forceinline__ void mma_tf32(float* c, const uint32_t* a, const uint32_t* b) {
    asm volatile(
        "mma.sync.aligned.m16n8k8.row.col.f32.tf32.tf32.f32 "
        "{%0,%1,%2,%3}, {%4,%5,%6,%7}, {%8,%9}, {%0,%1,%2,%3};"
        : "+f"(c[0]), "+f"(c[1]), "+f"(c[2]), "+f"(c[3])
        : "r"(a[0]), "r"(a[1]), "r"(a[2]), "r"(a[3]), "r"(b[0]), "r"(b[1]));
}
__device__ __forceinline__ void mma_f16(float* c, const uint32_t* a, const uint32_t* b) {
    asm volatile(
        "mma.sync.aligned.m16n8k16.row.col.f32.f16.f16.f32 "
        "{%0,%1,%2,%3}, {%4,%5,%6,%7}, {%8,%9}, {%0,%1,%2,%3};"
        : "+f"(c[0]), "+f"(c[1]), "+f"(c[2]), "+f"(c[3])
        : "r"(a[0]), "r"(a[1]), "r"(a[2]), "r"(a[3]), "r"(b[0]), "r"(b[1]));
}
__device__ __forceinline__ float gelu_f(float x) {
    float x3 = x * x * x;
    float t = tanhf(0.7978845608028654f * (x + 0.044715f * x3));
    return 0.5f * x * (1.0f + t);
}

// ---------------- LayerNorm (plain fp32 output; GEMM loaders convert) ----------------
__global__ void ln_k(const float* __restrict__ in, const float* __restrict__ sc,
                     const float* __restrict__ bi, float* __restrict__ out) {
    __shared__ float xs[Dc];
    __shared__ float red[256];
    int t = blockIdx.x, tid = threadIdx.x;
    const float* r = in + (size_t)t * Dc;
    float s = 0.f;
    for (int d = tid; d < Dc; d += 256) { float v = r[d]; xs[d] = v; s += v; }
    red[tid] = s; __syncthreads();
    for (int o = 128; o > 0; o >>= 1) { if (tid < o) red[tid] += red[tid + o]; __syncthreads(); }
    float mu = red[0] * (1.0f / Dc);
    __syncthreads();
    float s2 = 0.f;
    for (int d = tid; d < Dc; d += 256) { float dv = xs[d] - mu; s2 += dv * dv; }
    red[tid] = s2; __syncthreads();
    for (int o = 128; o > 0; o >>= 1) { if (tid < o) red[tid] += red[tid + o]; __syncthreads(); }
    float inv = rsqrtf(red[0] * (1.0f / Dc) + 1e-6f);
    float* orow = out + (size_t)t * Dc;
    for (int d = tid; d < Dc; d += 256)
        orow[d] = (xs[d] - mu) * inv * sc[d] + bi[d];
}

// ---------------- FP16 mma.sync GEMM: 128x64 tile, 8 warps x 32x32, m16n8k16 ------
// fp32 in/out; loader converts to fp16 (same 10-bit mantissa as tf32).
// A smem [row][ASTRh] halfs; B smem [kpair][n*2] halfs, stride BSTRh (both
// layouts bank-conflict-free for the fragment read patterns).
// blockIdx.z expert batching. EPI: 0 bias; 1 bias+res; 2 bias+gelu.
// ROUND: tf32-round C (only needed when C feeds the tf32 attention kernel).
#define TBM 128
#define TBN 64
#define TBK 32
#define ASTRh 40                       // halfs per A row
#define BSTRh 144                      // halfs per B k-pair row
#define ABUFh (TBM*ASTRh)              // 5120 halfs
#define BBUFh (16*BSTRh)               // 2304 halfs (16 k-pairs)
#define STAGEh (ABUFh + BBUFh)         // 7424 halfs = 14848 B
#define TGEMM_SMEM (2*STAGEh*2)        // 29696 B

template<int EPI, bool GATHER, int ROUND>
__global__ __launch_bounds__(256, 2) void tmma_k(
    const float* __restrict__ A, const float* __restrict__ B,
    const float* __restrict__ bias, const float* __restrict__ res,
    float* __restrict__ C, int M, int N, int Kd,
    const int* __restrict__ ridx, const int* __restrict__ mcnt,
    size_t aStrideZ, size_t bStrideZ, int biasStrideZ, size_t cStrideZ, int ridxStrideZ)
{
    int ez = blockIdx.z;
    A    += (size_t)ez * aStrideZ;
    B    += (size_t)ez * bStrideZ;
    bias += (size_t)ez * biasStrideZ;
    C    += (size_t)ez * cStrideZ;
    if (GATHER) ridx += (size_t)ez * ridxStrideZ;

    int Meff = mcnt ? mcnt[ez] : M;
    int row0 = blockIdx.y * TBM;
    if (row0 >= Meff) return;
    int col0 = blockIdx.x * TBN;

    extern __shared__ __align__(16) char smraw[];
    __half* sh = (__half*)smraw;

    int tid  = threadIdx.x;
    int wid  = tid >> 5;
    int lane = tid & 31;

    // ---- loader setup: 256 threads, 4 A-float4 + 2 B-float4 each ----
    const float* arow[4];
    int ar = tid >> 3;            // 0..31
    int ac4 = tid & 7;            // 0..7
#pragma unroll
    for (int i = 0; i < 4; i++) {
        int gr = row0 + i * 32 + ar;
        int cr = gr < Meff ? gr : Meff - 1;
        int src = GATHER ? ridx[cr] : cr;
        arow[i] = A + (size_t)src * Kd + ac4 * 4;
    }
    const float* bptr = B + (size_t)ar * N + col0 + ac4 * 4;

    float4 aR[4]; float4 bR[2];
    auto gload = [&](int c) {
        int k0 = c * TBK;
#pragma unroll
        for (int i = 0; i < 4; i++) aR[i] = *(const float4*)(arow[i] + k0);
#pragma unroll
        for (int i = 0; i < 2; i++) bR[i] = *(const float4*)(bptr + (size_t)k0 * N + i * 32);
    };
    int kp = ar >> 1, ko = ar & 1;
    auto sstore = [&](int b) {
        __half* Ah = sh + b * STAGEh;
        __half* Bh = Ah + ABUFh;
#pragma unroll
        for (int i = 0; i < 4; i++) {
            uint2 v = make_uint2(f2h2(aR[i].x, aR[i].y), f2h2(aR[i].z, aR[i].w));
            *(uint2*)(Ah + (i * 32 + ar) * ASTRh + ac4 * 4) = v;
        }
        __half* bp = Bh + kp * BSTRh + ko;
#pragma unroll
        for (int i = 0; i < 2; i++) {
            int nl = ac4 * 4 + i * 32;
            bp[(nl + 0) * 2] = __float2half_rn(bR[i].x);
            bp[(nl + 1) * 2] = __float2half_rn(bR[i].y);
            bp[(nl + 2) * 2] = __float2half_rn(bR[i].z);
            bp[(nl + 3) * 2] = __float2half_rn(bR[i].w);
        }
    };

    // ---- compute setup ----
    int g = lane >> 2, t = lane & 3;
    int m0 = (wid & 3) * 32;
    int n0 = (wid >> 2) * 32;
    float acc[2][4][4];
#pragma unroll
    for (int mt = 0; mt < 2; mt++)
#pragma unroll
        for (int nt = 0; nt < 4; nt++)
#pragma unroll
            for (int i = 0; i < 4; i++) acc[mt][nt][i] = 0.f;

    auto compute = [&](int b) {
        const __half* Ah = sh + b * STAGEh;
        const __half* Bh = Ah + ABUFh;
#pragma unroll
        for (int kk2 = 0; kk2 < 2; kk2++) {      // 2 x k16
            uint32_t af[2][4], bf[4][2];
#pragma unroll
            for (int mt = 0; mt < 2; mt++) {
                const __half* ap = Ah + (m0 + mt * 16 + g) * ASTRh + kk2 * 16 + 2 * t;
                af[mt][0] = *(const uint32_t*)(ap);
                af[mt][1] = *(const uint32_t*)(ap + 8 * ASTRh);
                af[mt][2] = *(const uint32_t*)(ap + 8);
                af[mt][3] = *(const uint32_t*)(ap + 8 * ASTRh + 8);
            }
#pragma unroll
            for (int nt = 0; nt < 4; nt++) {
                int nb = n0 + nt * 8 + g;
                int p  = kk2 * 8 + t;
                bf[nt][0] = *(const uint32_t*)(Bh + p * BSTRh + nb * 2);
                bf[nt][1] = *(const uint32_t*)(Bh + (p + 4) * BSTRh + nb * 2);
            }
#pragma unroll
            for (int mt = 0; mt < 2; mt++)
#pragma unroll
                for (int nt = 0; nt < 4; nt++)
                    mma_f16(acc[mt][nt], af[mt], bf[nt]);
        }
    };

    // ---- pipelined main loop: ONE sync per chunk (R7-proven hazard analysis) ----
    const int NC = Kd / TBK;
    gload(0); sstore(0);
    __syncthreads();
    for (int c = 0; c < NC; c++) {
        if (c + 1 < NC) gload(c + 1);
        compute(c & 1);
        if (c + 1 < NC) sstore((c + 1) & 1);
        __syncthreads();
    }

    // ---- epilogue (fragment mapping identical to tf32 m16n8) ----
#pragma unroll
    for (int mt = 0; mt < 2; mt++) {
#pragma unroll
        for (int hrow = 0; hrow < 2; hrow++) {
            int gr = row0 + m0 + mt * 16 + hrow * 8 + g;
            if (gr >= Meff) continue;
            float* crow = C + (size_t)gr * N;
            const float* rrow = (EPI == 1) ? (res + (size_t)gr * N) : nullptr;
#pragma unroll
            for (int nt = 0; nt < 4; nt++) {
                int gc = col0 + n0 + nt * 8 + 2 * t;
                float v0 = acc[mt][nt][hrow * 2 + 0] + bias[gc];
                float v1 = acc[mt][nt][hrow * 2 + 1] + bias[gc + 1];
                if (EPI == 1) { v0 += rrow[gc]; v1 += rrow[gc + 1]; }
                if (EPI == 2) { v0 = gelu_f(v0); v1 = gelu_f(v1); }
                if (ROUND)    { v0 = f2tf32f(v0); v1 = f2tf32f(v1); }
                *(float2*)(crow + gc) = make_float2(v0, v1);
            }
        }
    }
}

// ---------------- TF32 tensor-core causal flash attention (R12, unchanged) --------
#define QT 128
#define KT 64
#define KSTR 68
#define ATT_SMEM ((QT*KSTR + 2*KT*KSTR) * 4)

__global__ __launch_bounds__(256) void attn_tc_k(
    const float* __restrict__ q, const float* __restrict__ k,
    const float* __restrict__ v, float* __restrict__ o)
{
    extern __shared__ float sm[];
    float* Qs = sm;
    float* Ks = sm + QT * KSTR;
    float* Vs = sm + QT * KSTR + KT * KSTR;
    float* Ps = Qs;

    int bh = blockIdx.y;
    int b = bh >> 4, h = bh & 15;
    int qb = blockIdx.x * QT;
    int tid = threadIdx.x, wid = tid >> 5, lane = tid & 31;
    int g = lane >> 2, t = lane & 3;
    size_t base = ((size_t)b * Sc) * Dc + h * DHc;

#pragma unroll
    for (int i = 0; i < 8; i++) {
        int idx = tid + i * 256;
        int r = idx >> 4, c4 = (idx & 15) * 4;
        float4 val = *(const float4*)(q + base + (size_t)(qb + r) * Dc + c4);
        val.x *= 0.125f; val.y *= 0.125f; val.z *= 0.125f; val.w *= 0.125f;
        *(float4*)(Qs + r * KSTR + c4) = val;
    }
    __syncthreads();

    int qrow = wid * 16;
    uint32_t qf[8][4];
    {
        const uint32_t* Q32 = (const uint32_t*)Qs;
#pragma unroll
        for (int kc = 0; kc < 8; kc++) {
            int base0 = (qrow + g) * KSTR + kc * 8 + t;
            qf[kc][0] = Q32[base0];
            qf[kc][1] = Q32[base0 + 8 * KSTR];
            qf[kc][2] = Q32[base0 + 4];
            qf[kc][3] = Q32[base0 + 8 * KSTR + 4];
        }
    }
    __syncthreads();

    float oa[8][4];
#pragma unroll
    for (int nt = 0; nt < 8; nt++)
#pragma unroll
        for (int i = 0; i < 4; i++) oa[nt][i] = 0.f;
    float m0 = -1e30f, m1 = -1e30f, l0 = 0.f, l1 = 0.f;
    int r0 = qb + qrow + g, r1 = r0 + 8;

    int ntiles = qb / KT + 2;
    float* Pw = Ps + wid * 16 * KSTR;
    uint32_t* Pw32 = (uint32_t*)Pw;
    const uint32_t* K32 = (const uint32_t*)Ks;
    const uint32_t* V32 = (const uint32_t*)Vs;

    for (int tile = 0; tile < ntiles; tile++) {
        int j0 = tile * KT;
        __syncthreads();
#pragma unroll
        for (int i = 0; i < 4; i++) {
            int idx = tid + i * 256;
            int r = idx >> 4, c4 = (idx & 15) * 4;
            size_t goff = base + (size_t)(j0 + r) * Dc + c4;
            *(float4*)(Ks + r * KSTR + c4) = *(const float4*)(k + goff);
            *(float4*)(Vs + r * KSTR + c4) = *(const float4*)(v + goff);
        }
        __syncthreads();

        if (j0 > qb + qrow + 15) continue;

        float s[8][4];
#pragma unroll
        for (int nt = 0; nt < 8; nt++) {
            s[nt][0] = s[nt][1] = s[nt][2] = s[nt][3] = 0.f;
            const uint32_t* krow = K32 + (nt * 8 + g) * KSTR;
#pragma unroll
            for (int kc = 0; kc < 8; kc++) {
                uint32_t bf[2] = { krow[kc * 8 + t], krow[kc * 8 + t + 4] };
                mma_tf32(s[nt], qf[kc], bf);
            }
        }
        if (j0 + KT - 1 > qb + qrow) {
#pragma unroll
            for (int nt = 0; nt < 8; nt++) {
                int cbp = j0 + nt * 8 + 2 * t;
                if (cbp > r0)     s[nt][0] = -1e30f;
                if (cbp + 1 > r0) s[nt][1] = -1e30f;
                if (cbp > r1)     s[nt][2] = -1e30f;
                if (cbp + 1 > r1) s[nt][3] = -1e30f;
            }
        }
        float mt0 = -1e30f, mt1 = -1e30f;
#pragma unroll
        for (int nt = 0; nt < 8; nt++) {
            mt0 = fmaxf(mt0, fmaxf(s[nt][0], s[nt][1]));
            mt1 = fmaxf(mt1, fmaxf(s[nt][2], s[nt][3]));
        }
#pragma unroll
        for (int off = 1; off <= 2; off <<= 1) {
            mt0 = fmaxf(mt0, __shfl_xor_sync(0xffffffffu, mt0, off));
            mt1 = fmaxf(mt1, __shfl_xor_sync(0xffffffffu, mt1, off));
        }
        float mn0 = fmaxf(m0, mt0), mn1 = fmaxf(m1, mt1);
        float c0 = __expf(m0 - mn0), c1 = __expf(m1 - mn1);
        m0 = mn0; m1 = mn1;
        l0 *= c0; l1 *= c1;
#pragma unroll
        for (int nt = 0; nt < 8; nt++) {
            oa[nt][0] *= c0; oa[nt][1] *= c0;
            oa[nt][2] *= c1; oa[nt][3] *= c1;
        }
#pragma unroll
        for (int nt = 0; nt < 8; nt++) {
            float p0 = __expf(s[nt][0] - m0);
            float p1 = __expf(s[nt][1] - m0);
            float p2 = __expf(s[nt][2] - m1);
            float p3 = __expf(s[nt][3] - m1);
            l0 += p0 + p1; l1 += p2 + p3;
            int cbp = nt * 8 + 2 * t;
            *(uint2*)(Pw32 + g * KSTR + cbp)       = make_uint2(f2tf32(p0), f2tf32(p1));
            *(uint2*)(Pw32 + (g + 8) * KSTR + cbp) = make_uint2(f2tf32(p2), f2tf32(p3));
        }
        __syncwarp();
        uint32_t af[8][4];
#pragma unroll
        for (int kc = 0; kc < 8; kc++) {
            int base0 = g * KSTR + kc * 8 + t;
            af[kc][0] = Pw32[base0];
            af[kc][1] = Pw32[base0 + 8 * KSTR];
            af[kc][2] = Pw32[base0 + 4];
            af[kc][3] = Pw32[base0 + 8 * KSTR + 4];
        }
#pragma unroll
        for (int nt = 0; nt < 8; nt++) {
#pragma unroll
            for (int kc = 0; kc < 8; kc++) {
                uint32_t bf[2] = { V32[(kc * 8 + t) * KSTR + nt * 8 + g],
                                   V32[(kc * 8 + t + 4) * KSTR + nt * 8 + g] };
                mma_tf32(oa[nt], af[kc], bf);
            }
        }
        __syncwarp();
    }

#pragma unroll
    for (int off = 1; off <= 2; off <<= 1) {
        l0 += __shfl_xor_sync(0xffffffffu, l0, off);
        l1 += __shfl_xor_sync(0xffffffffu, l1, off);
    }
    float i0 = 1.f / l0, i1 = 1.f / l1;
    float* o0 = o + base + (size_t)r0 * Dc;
    float* o1 = o + base + (size_t)r1 * Dc;
#pragma unroll
    for (int nt = 0; nt < 8; nt++) {
        int cbp = nt * 8 + 2 * t;
        *(float2*)(o0 + cbp) = make_float2(f2tf32f(oa[nt][0] * i0), f2tf32f(oa[nt][1] * i0));
        *(float2*)(o1 + cbp) = make_float2(f2tf32f(oa[nt][2] * i1), f2tf32f(oa[nt][3] * i1));
    }
}

// ---------------- MoE routing (consumes fp32 ln2) ----------------
__global__ void route_k(const float* __restrict__ ln2,
                        const float* __restrict__ Wg, const float* __restrict__ bg) {
    int t = blockIdx.x;
    int tid = threadIdx.x;
    int w = tid >> 5, lane = tid & 31;
    const float* xr = ln2 + (size_t)t * Dc;
    float s = 0.f;
    for (int d = lane; d < Dc; d += 32) s += xr[d] * Wg[d * Ec + w];
#pragma unroll
    for (int off = 16; off > 0; off >>= 1) s += __shfl_down_sync(0xffffffffu, s, off);
    __shared__ float lg[Ec];
    if (lane == 0) lg[w] = s + bg[w];
    __syncthreads();
    if (tid == 0) {
        float mx = lg[0];
        for (int e = 1; e < Ec; e++) mx = fmaxf(mx, lg[e]);
        float p[Ec]; float sum = 0.f;
        for (int e = 0; e < Ec; e++) { p[e] = __expf(lg[e] - mx); sum += p[e]; }
        float inv = 1.f / sum;
        for (int e = 0; e < Ec; e++) { p[e] *= inv; atomicAdd(&g_pmean[e], p[e]); }
        int e0 = 0; for (int e = 1; e < Ec; e++) if (p[e] > p[e0]) e0 = e;
        int e1 = (e0 == 0) ? 1 : 0;
        for (int e = 0; e < Ec; e++) if (e != e0 && p[e] > p[e1]) e1 = e;
        float w0 = p[e0], w1 = p[e1], wn = 1.f / (w0 + w1);
        w0 *= wn; w1 *= wn;
        int s0 = atomicAdd(&g_cnt[e0], 1);
        int s1 = atomicAdd(&g_cnt[e1], 1);
        g_list[e0 * Tc + s0] = t; g_list[e1 * Tc + s1] = t;
        g_te[2*t] = e0; g_te[2*t+1] = e1;
        g_pos[2*t] = s0; g_pos[2*t+1] = s1;
        g_tw[2*t] = w0; g_tw[2*t+1] = w1;
    }
}

// ---------------- combine & aux ----------------
__global__ void combine_k(float* __restrict__ out) {
    int t = blockIdx.x;
    int e0 = g_te[2*t], e1 = g_te[2*t+1];
    int s0 = g_pos[2*t], s1 = g_pos[2*t+1];
    float w0 = g_tw[2*t], w1 = g_tw[2*t+1];
    const float* y0 = g_y + ((size_t)e0 * Tc + s0) * Dc;
    const float* y1 = g_y + ((size_t)e1 * Tc + s1) * Dc;
    const float* r  = g_res1 + (size_t)t * Dc;
    float* o = out + (size_t)t * Dc;
    for (int d = threadIdx.x; d < Dc; d += 256)
        o[d] = r[d] + w0 * y0[d] + w1 * y1[d];
}

__global__ void aux_k(float* __restrict__ out) {
    if (threadIdx.x == 0) {
        float a = 0.f;
        for (int e = 0; e < Ec; e++) a += (float)g_cnt[e] * g_pmean[e];
        out[0] = 0.01f * (float)Ec * a / ((float)Tc * (float)Tc);
    }
}

// ---------------- launch ----------------
extern "C" void kernel_launch(void* const* d_in, const int* in_sizes, int n_in,
                              void* d_out, int out_size) {
    (void)in_sizes; (void)n_in;
    const float* x   = (const float*)d_in[0];
    const float* l1s = (const float*)d_in[1];
    const float* l1b = (const float*)d_in[2];
    const float* Wq  = (const float*)d_in[3];
    const float* bq  = (const float*)d_in[4];
    const float* Wk  = (const float*)d_in[5];
    const float* bk  = (const float*)d_in[6];
    const float* Wv  = (const float*)d_in[7];
    const float* bv  = (const float*)d_in[8];
    const float* Wo  = (const float*)d_in[9];
    const float* bo  = (const float*)d_in[10];
    const float* l2s = (const float*)d_in[11];
    const float* l2b = (const float*)d_in[12];
    const float* Wg  = (const float*)d_in[13];
    const float* bg  = (const float*)d_in[14];
    const float* W1  = (const float*)d_in[15];
    const float* b1  = (const float*)d_in[16];
    const float* W2  = (const float*)d_in[17];
    const float* b2  = (const float*)d_in[18];
    float* out = (float*)d_out;

    float *ln1, *qb_, *kb_, *vb_, *attn, *res1, *ln2, *hb, *yb;
    int *lst, *cnt;
    cudaGetSymbolAddress((void**)&ln1,  g_ln1);
    cudaGetSymbolAddress((void**)&qb_,  g_q);
    cudaGetSymbolAddress((void**)&kb_,  g_k);
    cudaGetSymbolAddress((void**)&vb_,  g_v);
    cudaGetSymbolAddress((void**)&attn, g_attn);
    cudaGetSymbolAddress((void**)&res1, g_res1);
    cudaGetSymbolAddress((void**)&ln2,  g_ln2);
    cudaGetSymbolAddress((void**)&hb,   g_h);
    cudaGetSymbolAddress((void**)&yb,   g_y);
    cudaGetSymbolAddress((void**)&lst,  g_list);
    cudaGetSymbolAddress((void**)&cnt,  g_cnt);

    cudaFuncSetAttribute((const void*)tmma_k<0,false,1>, cudaFuncAttributeMaxDynamicSharedMemorySize, TGEMM_SMEM);
    cudaFuncSetAttribute((const void*)tmma_k<1,false,0>, cudaFuncAttributeMaxDynamicSharedMemorySize, TGEMM_SMEM);
    cudaFuncSetAttribute((const void*)tmma_k<0,false,0>, cudaFuncAttributeMaxDynamicSharedMemorySize, TGEMM_SMEM);
    cudaFuncSetAttribute((const void*)tmma_k<2,true,0>,  cudaFuncAttributeMaxDynamicSharedMemorySize, TGEMM_SMEM);
    cudaFuncSetAttribute((const void*)attn_tc_k,         cudaFuncAttributeMaxDynamicSharedMemorySize, ATT_SMEM);

    init_k<<<1, 32>>>();
    ln_k<<<Tc, 256>>>(x, l1s, l1b, ln1);

    dim3 gD(Dc / TBN, Tc / TBM);   // (16, 32)
    tmma_k<0,false,1><<<gD, 256, TGEMM_SMEM>>>(ln1, Wq, bq, nullptr, qb_, Tc, Dc, Dc,
                                               nullptr, nullptr, 0, 0, 0, 0, 0);
    tmma_k<0,false,1><<<gD, 256, TGEMM_SMEM>>>(ln1, Wk, bk, nullptr, kb_, Tc, Dc, Dc,
                                               nullptr, nullptr, 0, 0, 0, 0, 0);
    tmma_k<0,false,1><<<gD, 256, TGEMM_SMEM>>>(ln1, Wv, bv, nullptr, vb_, Tc, Dc, Dc,
                                               nullptr, nullptr, 0, 0, 0, 0, 0);

    attn_tc_k<<<dim3(Sc / QT, Bc * Hc), 256, ATT_SMEM>>>(qb_, kb_, vb_, attn);

    tmma_k<1,false,0><<<gD, 256, TGEMM_SMEM>>>(attn, Wo, bo, x, res1, Tc, Dc, Dc,
                                               nullptr, nullptr, 0, 0, 0, 0, 0);
    ln_k<<<Tc, 256>>>(res1, l2s, l2b, ln2);
    route_k<<<Tc, 256>>>(ln2, Wg, bg);

    // ---- MoE: ALL experts in 2 launches via blockIdx.z ----
    dim3 gW1(FHc / TBN, Tc / TBM, Ec);   // (64, 32, 8)
    tmma_k<2,true,0><<<gW1, 256, TGEMM_SMEM>>>(
        ln2, W1, b1, nullptr, hb, Tc, FHc, Dc,
        lst, cnt,
        0, (size_t)Dc * FHc, FHc, (size_t)Tc * FHc, Tc);

    dim3 gW2(Dc / TBN, Tc / TBM, Ec);    // (16, 32, 8)
    tmma_k<0,false,0><<<gW2, 256, TGEMM_SMEM>>>(
        hb, W2, b2, nullptr, yb, Tc, Dc, FHc,
        nullptr, cnt,
        (size_t)Tc * FHc, (size_t)FHc * Dc, Dc, (size_t)Tc * Dc, 0);

    combine_k<<<Tc, 256>>>(out);
    if (out_size > Tc * Dc) aux_k<<<1, 32>>>(out + (size_t)Tc * Dc);
}